// round 5
// baseline (speedup 1.0000x reference)
#include <cuda_runtime.h>

#define N_NODES 100000
#define N_EDGES 1600000
#define IN_F    48
#define EDGE_F  32
#define HID_F   128
#define OUT_F   64
#define H0_F    96   // 2*IN_F

// ---------------- scratch (static device allocations only) ----------------
__device__ int   g_deg[N_NODES];
__device__ int   g_rowptr[N_NODES + 1];
__device__ int   g_cursor[N_NODES];
__device__ int   g_csr_src[N_EDGES];
__device__ int   g_csr_eid[N_EDGES];
__device__ float g_h  [N_NODES * H0_F];    // concat(nfeat, h_neigh0)
__device__ float g_hn1[N_NODES * H0_F];    // seg_mean(h[src])
__device__ float g_h1 [N_NODES * HID_F];   // layer1 output
__device__ float g_hn2[N_NODES * HID_F];   // seg_mean(h1[src])

// ---------------- CSR build ----------------
__global__ void k_deg(const int* __restrict__ dst) {
    int i = blockIdx.x * blockDim.x + threadIdx.x;
    if (i < N_EDGES) atomicAdd(&g_deg[dst[i]], 1);
}

// single-block exclusive scan of g_deg -> g_rowptr, g_cursor
__global__ void k_scan() {
    __shared__ int wsum[32];
    __shared__ int running;
    int t = threadIdx.x, lane = t & 31, w = t >> 5;
    if (t == 0) running = 0;
    __syncthreads();
    for (int base = 0; base < N_NODES; base += 1024) {
        int i = base + t;
        int v = (i < N_NODES) ? g_deg[i] : 0;
        int x = v;
        #pragma unroll
        for (int o = 1; o < 32; o <<= 1) {
            int y = __shfl_up_sync(0xffffffffu, x, o);
            if (lane >= o) x += y;
        }
        if (lane == 31) wsum[w] = x;
        __syncthreads();
        if (w == 0) {
            int s = wsum[lane];
            #pragma unroll
            for (int o = 1; o < 32; o <<= 1) {
                int y = __shfl_up_sync(0xffffffffu, s, o);
                if (lane >= o) s += y;
            }
            wsum[lane] = s;
        }
        __syncthreads();
        int excl = running + (w ? wsum[w - 1] : 0) + (x - v);
        if (i < N_NODES) { g_rowptr[i] = excl; g_cursor[i] = excl; }
        __syncthreads();
        if (t == 0) running += wsum[31];
        __syncthreads();
    }
    if (t == 0) g_rowptr[N_NODES] = running;
}

__global__ void k_fill(const int* __restrict__ src, const int* __restrict__ dst) {
    int i = blockIdx.x * blockDim.x + threadIdx.x;
    if (i < N_EDGES) {
        int d = dst[i];
        int p = atomicAdd(&g_cursor[d], 1);
        g_csr_src[p] = src[i];
        g_csr_eid[p] = i;
    }
}

// ---------------- fused edge encoder + u_mul_e + mean + concat ----------------
// one warp per destination node; edge-encoder weights held in registers per lane
__global__ void __launch_bounds__(256) k_layer0(
    const float* __restrict__ nfeat, const float* __restrict__ efeat,
    const float* __restrict__ We, const float* __restrict__ be)
{
    int gw = (blockIdx.x * blockDim.x + threadIdx.x) >> 5;
    int l  = threadIdx.x & 31;
    if (gw >= N_NODES) return;
    int f1 = l, f2 = 32 + l;
    bool v2 = (f2 < IN_F);           // lanes 0..15 handle a second output feature
    float w1[EDGE_F], w2[EDGE_F];
    #pragma unroll
    for (int k = 0; k < EDGE_F; k++) {
        w1[k] = We[k * IN_F + f1];
        w2[k] = v2 ? We[k * IN_F + f2] : 0.f;
    }
    float bb1 = be[f1], bb2 = v2 ? be[f2] : 0.f;

    int beg = g_rowptr[gw], end = g_rowptr[gw + 1];
    float acc1 = 0.f, acc2 = 0.f;
    for (int j = beg; j < end; j++) {
        int eid = g_csr_eid[j];
        int s   = g_csr_src[j];
        float ev = __ldg(&efeat[eid * EDGE_F + l]);   // lane l holds efeat[eid][l]
        float e1 = bb1, e2 = bb2;
        #pragma unroll
        for (int k = 0; k < EDGE_F; k++) {
            float ek = __shfl_sync(0xffffffffu, ev, k);
            e1 = fmaf(ek, w1[k], e1);
            e2 = fmaf(ek, w2[k], e2);
        }
        e1 = fmaxf(e1, 0.f);
        e2 = fmaxf(e2, 0.f);
        acc1 = fmaf(__ldg(&nfeat[s * IN_F + f1]), e1, acc1);
        if (v2) acc2 = fmaf(__ldg(&nfeat[s * IN_F + f2]), e2, acc2);
    }
    float inv = 1.f / fmaxf((float)(end - beg), 1.f);
    float* hr = &g_h[gw * H0_F];
    hr[f1]        = nfeat[gw * IN_F + f1];
    hr[IN_F + f1] = acc1 * inv;
    if (v2) {
        hr[f2]        = nfeat[gw * IN_F + f2];
        hr[IN_F + f2] = acc2 * inv;
    }
}

// ---------------- segment-mean gather (warp per node) ----------------
template <int F>
__device__ __forceinline__ void mean_impl(const float* __restrict__ in,
                                          float* __restrict__ out)
{
    int gw = (blockIdx.x * blockDim.x + threadIdx.x) >> 5;
    int l  = threadIdx.x & 31;
    if (gw >= N_NODES) return;
    constexpr int R = F / 32;
    float acc[R];
    #pragma unroll
    for (int r = 0; r < R; r++) acc[r] = 0.f;
    int beg = g_rowptr[gw], end = g_rowptr[gw + 1];
    for (int j = beg; j < end; j++) {
        int s = g_csr_src[j];
        const float* row = &in[s * F];
        #pragma unroll
        for (int r = 0; r < R; r++) acc[r] += __ldg(&row[r * 32 + l]);
    }
    float inv = 1.f / fmaxf((float)(end - beg), 1.f);
    #pragma unroll
    for (int r = 0; r < R; r++) out[gw * F + r * 32 + l] = acc[r] * inv;
}

__global__ void __launch_bounds__(256) k_mean96()  { mean_impl<H0_F>(g_h,  g_hn1); }
__global__ void __launch_bounds__(256) k_mean128() { mean_impl<HID_F>(g_h1, g_hn2); }

// ---------------- fused dual-GEMM: out = act(A1@Wa + A2@Wb + bias) ----------------
// BM=128 rows of nodes, full NOUT width, BK=32, 256 threads, 8 x (NOUT/16) micro-tile
template <int K, int NOUT, bool RELU, int LAYER>
__global__ void __launch_bounds__(256) k_gemm(
    const float* __restrict__ Wa, const float* __restrict__ Wb,
    const float* __restrict__ bias, float* __restrict__ outp)
{
    constexpr int BM = 128, BK = 32;
    constexpr int TN = NOUT / 16;
    __shared__ float As[BM][BK];
    __shared__ float Bs[BK][NOUT];

    const float* A1 = (LAYER == 1) ? g_h   : g_h1;
    const float* A2 = (LAYER == 1) ? g_hn1 : g_hn2;
    float* dstp     = (LAYER == 1) ? g_h1  : outp;

    int t  = threadIdx.x;
    int tx = t & 15, ty = t >> 4;
    int brow = blockIdx.x * BM;

    float acc[8][TN];
    #pragma unroll
    for (int m = 0; m < 8; m++)
        #pragma unroll
        for (int j = 0; j < TN; j++) acc[m][j] = 0.f;

    #pragma unroll
    for (int phase = 0; phase < 2; phase++) {
        const float* A = phase ? A2 : A1;
        const float* W = phase ? Wb : Wa;
        for (int kt = 0; kt < K; kt += BK) {
            // A tile: 128 x 32 floats
            #pragma unroll
            for (int i = 0; i < 4; i++) {
                int idx = t + i * 256;
                int r = idx >> 3, c4 = idx & 7;
                int grow = brow + r;
                float4 v = make_float4(0.f, 0.f, 0.f, 0.f);
                if (grow < N_NODES)
                    v = *(const float4*)&A[grow * K + kt + c4 * 4];
                *(float4*)&As[r][c4 * 4] = v;
            }
            // B tile: 32 x NOUT floats
            #pragma unroll
            for (int i = 0; i < NOUT / 32; i++) {
                int idx = t + i * 256;
                int r = idx / (NOUT / 4), c4 = idx % (NOUT / 4);
                *(float4*)&Bs[r][c4 * 4] = *(const float4*)&W[(kt + r) * NOUT + c4 * 4];
            }
            __syncthreads();
            #pragma unroll
            for (int k = 0; k < BK; k++) {
                float a[8], b[TN];
                #pragma unroll
                for (int m = 0; m < 8; m++) a[m] = As[ty * 8 + m][k];
                #pragma unroll
                for (int j = 0; j < TN; j++) b[j] = Bs[k][tx * TN + j];
                #pragma unroll
                for (int m = 0; m < 8; m++)
                    #pragma unroll
                    for (int j = 0; j < TN; j++)
                        acc[m][j] = fmaf(a[m], b[j], acc[m][j]);
            }
            __syncthreads();
        }
    }
    // epilogue
    #pragma unroll
    for (int m = 0; m < 8; m++) {
        int grow = brow + ty * 8 + m;
        if (grow < N_NODES) {
            #pragma unroll
            for (int j = 0; j < TN; j++) {
                float c = acc[m][j] + bias[tx * TN + j];
                if (RELU) c = fmaxf(c, 0.f);
                dstp[grow * NOUT + tx * TN + j] = c;
            }
        }
    }
}

// ---------------- launch ----------------
extern "C" void kernel_launch(void* const* d_in, const int* in_sizes, int n_in,
                              void* d_out, int out_size)
{
    const float* nfeat = (const float*)d_in[0];
    const float* efeat = (const float*)d_in[1];
    const int*   src   = (const int*)d_in[2];
    const int*   dst   = (const int*)d_in[3];
    const float* We    = (const float*)d_in[4];
    const float* be    = (const float*)d_in[5];
    const float* W1s   = (const float*)d_in[6];
    const float* W1n   = (const float*)d_in[7];
    const float* b1    = (const float*)d_in[8];
    const float* W2s   = (const float*)d_in[9];
    const float* W2n   = (const float*)d_in[10];
    const float* b2    = (const float*)d_in[11];
    float* out = (float*)d_out;

    const int WARP_GRID = (N_NODES * 32 + 255) / 256;   // warp-per-node kernels

    // zero degree counters (graph-capturable async memset on a static symbol)
    void* deg_ptr = nullptr;
    cudaGetSymbolAddress(&deg_ptr, g_deg);
    cudaMemsetAsync(deg_ptr, 0, N_NODES * sizeof(int));

    k_deg<<<(N_EDGES + 255) / 256, 256>>>(dst);
    k_scan<<<1, 1024>>>();
    k_fill<<<(N_EDGES + 255) / 256, 256>>>(src, dst);
    k_layer0<<<WARP_GRID, 256>>>(nfeat, efeat, We, be);
    k_mean96<<<WARP_GRID, 256>>>();
    k_gemm<H0_F, HID_F, true, 1><<<(N_NODES + 127) / 128, 256>>>(W1s, W1n, b1, nullptr);
    k_mean128<<<WARP_GRID, 256>>>();
    k_gemm<HID_F, OUT_F, false, 2><<<(N_NODES + 127) / 128, 256>>>(W2s, W2n, b2, out);
}

// round 6
// speedup vs baseline: 1.1067x; 1.1067x over previous
#include <cuda_runtime.h>

#define N_NODES 100000
#define N_EDGES 1600000
#define IN_F    48
#define EDGE_F  32
#define HID_F   128
#define OUT_F   64
#define H0_F    96   // 2*IN_F

// ---------------- scratch (static device allocations only) ----------------
__device__ int   g_deg[N_NODES];
__device__ int   g_rowptr[N_NODES + 1];
__device__ int   g_cursor[N_NODES];
__device__ int   g_csr_src[N_EDGES];
__device__ int   g_csr_eid[N_EDGES];
__device__ int   g_csr_dst[N_EDGES];
__device__ float g_hsum[N_NODES * IN_F];   // layer0 aggregated sums (pre-mean)
__device__ float g_h  [N_NODES * H0_F];    // concat(nfeat, h_neigh0)
__device__ float g_hn1[N_NODES * H0_F];    // seg_mean(h[src])
__device__ float g_h1 [N_NODES * HID_F];   // layer1 output
__device__ float g_hn2[N_NODES * HID_F];   // seg_mean(h1[src])

// ---------------- packed f32x2 helpers ----------------
__device__ __forceinline__ unsigned long long pack2(float lo, float hi) {
    unsigned long long u;
    asm("mov.b64 %0, {%1, %2};" : "=l"(u) : "f"(lo), "f"(hi));
    return u;
}
__device__ __forceinline__ float2 unpack2(unsigned long long u) {
    float lo, hi;
    asm("mov.b64 {%0, %1}, %2;" : "=f"(lo), "=f"(hi) : "l"(u));
    return make_float2(lo, hi);
}
__device__ __forceinline__ unsigned long long fma2(unsigned long long a,
                                                   unsigned long long b,
                                                   unsigned long long c) {
    unsigned long long d;
    asm("fma.rn.f32x2 %0, %1, %2, %3;" : "=l"(d) : "l"(a), "l"(b), "l"(c));
    return d;
}
__device__ __forceinline__ unsigned long long add2(unsigned long long a,
                                                   unsigned long long b) {
    unsigned long long d;
    asm("add.rn.f32x2 %0, %1, %2;" : "=l"(d) : "l"(a), "l"(b));
    return d;
}

// ---------------- CSR build ----------------
__global__ void k_deg(const int* __restrict__ dst) {
    int i = blockIdx.x * blockDim.x + threadIdx.x;
    if (i < N_EDGES) atomicAdd(&g_deg[dst[i]], 1);
}

// single-block exclusive scan of g_deg -> g_rowptr, g_cursor
__global__ void k_scan() {
    __shared__ int wsum[32];
    __shared__ int running;
    int t = threadIdx.x, lane = t & 31, w = t >> 5;
    if (t == 0) running = 0;
    __syncthreads();
    for (int base = 0; base < N_NODES; base += 1024) {
        int i = base + t;
        int v = (i < N_NODES) ? g_deg[i] : 0;
        int x = v;
        #pragma unroll
        for (int o = 1; o < 32; o <<= 1) {
            int y = __shfl_up_sync(0xffffffffu, x, o);
            if (lane >= o) x += y;
        }
        if (lane == 31) wsum[w] = x;
        __syncthreads();
        if (w == 0) {
            int s = wsum[lane];
            #pragma unroll
            for (int o = 1; o < 32; o <<= 1) {
                int y = __shfl_up_sync(0xffffffffu, s, o);
                if (lane >= o) s += y;
            }
            wsum[lane] = s;
        }
        __syncthreads();
        int excl = running + (w ? wsum[w - 1] : 0) + (x - v);
        if (i < N_NODES) { g_rowptr[i] = excl; g_cursor[i] = excl; }
        __syncthreads();
        if (t == 0) running += wsum[31];
        __syncthreads();
    }
    if (t == 0) g_rowptr[N_NODES] = running;
}

__global__ void k_fill(const int* __restrict__ src, const int* __restrict__ dst) {
    int i = blockIdx.x * blockDim.x + threadIdx.x;
    if (i < N_EDGES) {
        int d = dst[i];
        int p = atomicAdd(&g_cursor[d], 1);
        g_csr_src[p] = src[i];
        g_csr_eid[p] = i;
        g_csr_dst[p] = d;
    }
}

// ---------------- layer0: CSR-tiled edge GEMM + inline segment reduce ----------------
// Block processes 128 contiguous CSR slots. Thread = (col 0..47, chunk 0..3).
// Each thread: dot(efeat_row, We[:,col]) for 32 edges via packed f32x2 FMA,
// relu, multiply by gathered nfeat[src][col], serial segment-scan over its
// 32 sorted rows, flush partial sums with atomicAdd.
#define L0_TILE    128
#define L0_THREADS 192
__global__ void __launch_bounds__(L0_THREADS) k_layer0_gemm(
    const float* __restrict__ nfeat, const float* __restrict__ efeat,
    const float* __restrict__ We, const float* __restrict__ be)
{
    __shared__ ulonglong2 Es2[L0_TILE][9];   // 8 used, pad to 9 (anti-conflict)
    __shared__ float Ws[EDGE_F * IN_F];      // 32x48 weights
    __shared__ float bes[IN_F];
    __shared__ int   srcs_s[L0_TILE];
    __shared__ int   dsts_s[L0_TILE];
    __shared__ int   eids_s[L0_TILE];

    const int t  = threadIdx.x;
    const int j0 = blockIdx.x * L0_TILE;

    // phase 1: indices
    if (t < L0_TILE) {
        srcs_s[t] = g_csr_src[j0 + t];
        dsts_s[t] = g_csr_dst[j0 + t];
        eids_s[t] = g_csr_eid[j0 + t];
    }
    // weights + bias
    for (int idx = t; idx < EDGE_F * IN_F; idx += L0_THREADS) Ws[idx] = We[idx];
    if (t < IN_F) bes[t] = be[t];
    __syncthreads();

    // phase 2: gather efeat rows (128B per row, 16B vector loads)
    for (int idx = t; idx < L0_TILE * 8; idx += L0_THREADS) {
        int row = idx >> 3, q = idx & 7;
        const ulonglong2* er =
            (const ulonglong2*)(efeat + (size_t)eids_s[row] * EDGE_F);
        Es2[row][q] = er[q];
    }
    __syncthreads();

    const int col   = t % IN_F;     // 0..47
    const int chunk = t / IN_F;     // 0..3
    const int r0    = chunk * 32;

    // per-thread weight column, packed in k-pairs
    unsigned long long wk2[EDGE_F / 2];
    #pragma unroll
    for (int p = 0; p < EDGE_F / 2; p++)
        wk2[p] = pack2(Ws[(2 * p) * IN_F + col], Ws[(2 * p + 1) * IN_F + col]);
    const float bcol = bes[col];

    int   cur = dsts_s[r0];
    float sum = 0.f;
    #pragma unroll 2
    for (int r = r0; r < r0 + 32; r++) {
        unsigned long long accA = pack2(bcol, 0.f);
        unsigned long long accB = pack2(0.f, 0.f);
        #pragma unroll
        for (int q = 0; q < 8; q++) {
            ulonglong2 a = Es2[r][q];
            accA = fma2(a.x, wk2[2 * q],     accA);
            accB = fma2(a.y, wk2[2 * q + 1], accB);
        }
        float2 f = unpack2(add2(accA, accB));
        float e  = fmaxf(f.x + f.y, 0.f);
        float m  = e * __ldg(&nfeat[(size_t)srcs_s[r] * IN_F + col]);
        int d = dsts_s[r];
        if (d != cur) {
            atomicAdd(&g_hsum[(size_t)cur * IN_F + col], sum);
            sum = 0.f;
            cur = d;
        }
        sum += m;
    }
    atomicAdd(&g_hsum[(size_t)cur * IN_F + col], sum);
}

// divide by degree + build concat h = [nfeat | mean]
__global__ void k_finalize0(const float* __restrict__ nfeat) {
    int i = blockIdx.x * blockDim.x + threadIdx.x;
    if (i >= N_NODES * IN_F) return;
    int n = i / IN_F, c = i % IN_F;
    int deg = g_rowptr[n + 1] - g_rowptr[n];
    float inv = 1.f / fmaxf((float)deg, 1.f);
    g_h[n * H0_F + c]        = nfeat[i];
    g_h[n * H0_F + IN_F + c] = g_hsum[i] * inv;
}

// ---------------- segment-mean gather (warp per node) ----------------
template <int F>
__device__ __forceinline__ void mean_impl(const float* __restrict__ in,
                                          float* __restrict__ out)
{
    int gw = (blockIdx.x * blockDim.x + threadIdx.x) >> 5;
    int l  = threadIdx.x & 31;
    if (gw >= N_NODES) return;
    constexpr int R = F / 32;
    float acc[R];
    #pragma unroll
    for (int r = 0; r < R; r++) acc[r] = 0.f;
    int beg = g_rowptr[gw], end = g_rowptr[gw + 1];
    for (int j = beg; j < end; j++) {
        int s = g_csr_src[j];
        const float* row = &in[s * F];
        #pragma unroll
        for (int r = 0; r < R; r++) acc[r] += __ldg(&row[r * 32 + l]);
    }
    float inv = 1.f / fmaxf((float)(end - beg), 1.f);
    #pragma unroll
    for (int r = 0; r < R; r++) out[gw * F + r * 32 + l] = acc[r] * inv;
}

__global__ void __launch_bounds__(256) k_mean96()  { mean_impl<H0_F>(g_h,  g_hn1); }
__global__ void __launch_bounds__(256) k_mean128() { mean_impl<HID_F>(g_h1, g_hn2); }

// ---------------- fused dual-GEMM: out = act(A1@Wa + A2@Wb + bias) ----------------
template <int K, int NOUT, bool RELU, int LAYER>
__global__ void __launch_bounds__(256) k_gemm(
    const float* __restrict__ Wa, const float* __restrict__ Wb,
    const float* __restrict__ bias, float* __restrict__ outp)
{
    constexpr int BM = 128, BK = 32;
    constexpr int TN = NOUT / 16;
    __shared__ float As[BM][BK];
    __shared__ float Bs[BK][NOUT];

    const float* A1 = (LAYER == 1) ? g_h   : g_h1;
    const float* A2 = (LAYER == 1) ? g_hn1 : g_hn2;
    float* dstp     = (LAYER == 1) ? g_h1  : outp;

    int t  = threadIdx.x;
    int tx = t & 15, ty = t >> 4;
    int brow = blockIdx.x * BM;

    float acc[8][TN];
    #pragma unroll
    for (int m = 0; m < 8; m++)
        #pragma unroll
        for (int j = 0; j < TN; j++) acc[m][j] = 0.f;

    #pragma unroll
    for (int phase = 0; phase < 2; phase++) {
        const float* A = phase ? A2 : A1;
        const float* W = phase ? Wb : Wa;
        for (int kt = 0; kt < K; kt += BK) {
            #pragma unroll
            for (int i = 0; i < 4; i++) {
                int idx = t + i * 256;
                int r = idx >> 3, c4 = idx & 7;
                int grow = brow + r;
                float4 v = make_float4(0.f, 0.f, 0.f, 0.f);
                if (grow < N_NODES)
                    v = *(const float4*)&A[grow * K + kt + c4 * 4];
                *(float4*)&As[r][c4 * 4] = v;
            }
            #pragma unroll
            for (int i = 0; i < NOUT / 32; i++) {
                int idx = t + i * 256;
                int r = idx / (NOUT / 4), c4 = idx % (NOUT / 4);
                *(float4*)&Bs[r][c4 * 4] = *(const float4*)&W[(kt + r) * NOUT + c4 * 4];
            }
            __syncthreads();
            #pragma unroll
            for (int k = 0; k < BK; k++) {
                float a[8], b[TN];
                #pragma unroll
                for (int m = 0; m < 8; m++) a[m] = As[ty * 8 + m][k];
                #pragma unroll
                for (int j = 0; j < TN; j++) b[j] = Bs[k][tx * TN + j];
                #pragma unroll
                for (int m = 0; m < 8; m++)
                    #pragma unroll
                    for (int j = 0; j < TN; j++)
                        acc[m][j] = fmaf(a[m], b[j], acc[m][j]);
            }
            __syncthreads();
        }
    }
    #pragma unroll
    for (int m = 0; m < 8; m++) {
        int grow = brow + ty * 8 + m;
        if (grow < N_NODES) {
            #pragma unroll
            for (int j = 0; j < TN; j++) {
                float c = acc[m][j] + bias[tx * TN + j];
                if (RELU) c = fmaxf(c, 0.f);
                dstp[grow * NOUT + tx * TN + j] = c;
            }
        }
    }
}

// ---------------- launch ----------------
extern "C" void kernel_launch(void* const* d_in, const int* in_sizes, int n_in,
                              void* d_out, int out_size)
{
    const float* nfeat = (const float*)d_in[0];
    const float* efeat = (const float*)d_in[1];
    const int*   src   = (const int*)d_in[2];
    const int*   dst   = (const int*)d_in[3];
    const float* We    = (const float*)d_in[4];
    const float* be    = (const float*)d_in[5];
    const float* W1s   = (const float*)d_in[6];
    const float* W1n   = (const float*)d_in[7];
    const float* b1    = (const float*)d_in[8];
    const float* W2s   = (const float*)d_in[9];
    const float* W2n   = (const float*)d_in[10];
    const float* b2    = (const float*)d_in[11];
    float* out = (float*)d_out;

    const int WARP_GRID = (N_NODES * 32 + 255) / 256;

    void* p = nullptr;
    cudaGetSymbolAddress(&p, g_deg);
    cudaMemsetAsync(p, 0, N_NODES * sizeof(int));
    cudaGetSymbolAddress(&p, g_hsum);
    cudaMemsetAsync(p, 0, (size_t)N_NODES * IN_F * sizeof(float));

    k_deg<<<(N_EDGES + 255) / 256, 256>>>(dst);
    k_scan<<<1, 1024>>>();
    k_fill<<<(N_EDGES + 255) / 256, 256>>>(src, dst);
    k_layer0_gemm<<<N_EDGES / L0_TILE, L0_THREADS>>>(nfeat, efeat, We, be);
    k_finalize0<<<(N_NODES * IN_F + 255) / 256, 256>>>(nfeat);
    k_mean96<<<WARP_GRID, 256>>>();
    k_gemm<H0_F, HID_F, true, 1><<<(N_NODES + 127) / 128, 256>>>(W1s, W1n, b1, nullptr);
    k_mean128<<<WARP_GRID, 256>>>();
    k_gemm<HID_F, OUT_F, false, 2><<<(N_NODES + 127) / 128, 256>>>(W2s, W2n, b2, out);
}

// round 8
// speedup vs baseline: 1.5205x; 1.3739x over previous
#include <cuda_runtime.h>

#define N_NODES 100000
#define N_EDGES 1600000
#define IN_F    48
#define EDGE_F  32
#define HID_F   128
#define OUT_F   64
#define H0_F    96   // 2*IN_F

// ---------------- scratch (static device allocations only) ----------------
__device__ int   g_deg[N_NODES];
__device__ int   g_rowptr[N_NODES + 1];
__device__ int   g_cursor[N_NODES];
__device__ int   g_csr_src[N_EDGES];
__device__ int   g_csr_eid[N_EDGES];
__device__ int   g_csr_dst[N_EDGES];
__device__ float g_hsum[N_NODES * IN_F];   // layer0 aggregated sums (pre-mean)
__device__ float g_h  [N_NODES * H0_F];    // concat(nfeat, h_neigh0)
__device__ float g_hn1[N_NODES * H0_F];    // seg_mean(h[src])
__device__ float g_h1 [N_NODES * HID_F];   // layer1 output
__device__ float g_s2z[N_NODES * 128];     // [h1@W2s+b2 | h1@W2n]

// ---------------- packed f32x2 helpers ----------------
__device__ __forceinline__ unsigned long long pack2(float lo, float hi) {
    unsigned long long u;
    asm("mov.b64 %0, {%1, %2};" : "=l"(u) : "f"(lo), "f"(hi));
    return u;
}
__device__ __forceinline__ float2 unpack2(unsigned long long u) {
    float lo, hi;
    asm("mov.b64 {%0, %1}, %2;" : "=f"(lo), "=f"(hi) : "l"(u));
    return make_float2(lo, hi);
}
__device__ __forceinline__ unsigned long long fma2(unsigned long long a,
                                                   unsigned long long b,
                                                   unsigned long long c) {
    unsigned long long d;
    asm("fma.rn.f32x2 %0, %1, %2, %3;" : "=l"(d) : "l"(a), "l"(b), "l"(c));
    return d;
}

// ---------------- CSR build ----------------
__global__ void k_deg(const int* __restrict__ dst) {
    int i = blockIdx.x * blockDim.x + threadIdx.x;
    if (i < N_EDGES) atomicAdd(&g_deg[dst[i]], 1);
}

__global__ void k_scan() {
    __shared__ int wsum[32];
    __shared__ int running;
    int t = threadIdx.x, lane = t & 31, w = t >> 5;
    if (t == 0) running = 0;
    __syncthreads();
    for (int base = 0; base < N_NODES; base += 1024) {
        int i = base + t;
        int v = (i < N_NODES) ? g_deg[i] : 0;
        int x = v;
        #pragma unroll
        for (int o = 1; o < 32; o <<= 1) {
            int y = __shfl_up_sync(0xffffffffu, x, o);
            if (lane >= o) x += y;
        }
        if (lane == 31) wsum[w] = x;
        __syncthreads();
        if (w == 0) {
            int s = wsum[lane];
            #pragma unroll
            for (int o = 1; o < 32; o <<= 1) {
                int y = __shfl_up_sync(0xffffffffu, s, o);
                if (lane >= o) s += y;
            }
            wsum[lane] = s;
        }
        __syncthreads();
        int excl = running + (w ? wsum[w - 1] : 0) + (x - v);
        if (i < N_NODES) { g_rowptr[i] = excl; g_cursor[i] = excl; }
        __syncthreads();
        if (t == 0) running += wsum[31];
        __syncthreads();
    }
    if (t == 0) g_rowptr[N_NODES] = running;
}

__global__ void k_fill(const int* __restrict__ src, const int* __restrict__ dst) {
    int i = blockIdx.x * blockDim.x + threadIdx.x;
    if (i < N_EDGES) {
        int d = dst[i];
        int p = atomicAdd(&g_cursor[d], 1);
        g_csr_src[p] = src[i];
        g_csr_eid[p] = i;
        g_csr_dst[p] = d;
    }
}

// ---------------- layer0: register-tiled edge GEMM + segment reduce ----------------
// Block = 256 CSR slots. 192 threads: 32 row-tiles(8) x 6 col-tiles(8).
// E = relu(efeat@We + be); m = E * nfeat[src]; atomic segment-sum into g_hsum.
#define L0_TILE    256
#define L0_THREADS 192
#define L0_APAD    260    // 256 + 4 (stride%32==4; swizzle handles the rest)

__global__ void __launch_bounds__(L0_THREADS) k_layer0_gemm(
    const float* __restrict__ nfeat, const float* __restrict__ efeat,
    const float* __restrict__ We, const float* __restrict__ be)
{
    __shared__ float AsT[EDGE_F][L0_APAD];   // k-major efeat tile, swizzled
    __shared__ float Bs[EDGE_F][IN_F];       // 32x48 weights
    __shared__ float bes[IN_F];
    __shared__ int   srcs_s[L0_TILE];
    __shared__ int   dsts_s[L0_TILE];
    __shared__ int   eids_s[L0_TILE];

    const int t  = threadIdx.x;
    const int j0 = blockIdx.x * L0_TILE;

    for (int idx = t; idx < L0_TILE; idx += L0_THREADS) {
        srcs_s[idx] = g_csr_src[j0 + idx];
        dsts_s[idx] = g_csr_dst[j0 + idx];
        eids_s[idx] = g_csr_eid[j0 + idx];
    }
    for (int idx = t; idx < EDGE_F * IN_F / 4; idx += L0_THREADS) {
        int r = idx / 12, c4 = idx % 12;
        *(float4*)&Bs[r][c4 * 4] = *(const float4*)&We[r * IN_F + c4 * 4];
    }
    if (t < IN_F) bes[t] = be[t];
    __syncthreads();

    // gather efeat rows -> AsT (k-major, swizzled: pos = row ^ (8*(c4&3)))
    for (int idx = t; idx < L0_TILE * 8; idx += L0_THREADS) {
        int row = idx >> 3, c4 = idx & 7;
        float4 v = *(const float4*)&efeat[(size_t)eids_s[row] * EDGE_F + c4 * 4];
        int pos = row ^ (8 * (c4 & 3));
        AsT[4 * c4 + 0][pos] = v.x;
        AsT[4 * c4 + 1][pos] = v.y;
        AsT[4 * c4 + 2][pos] = v.z;
        AsT[4 * c4 + 3][pos] = v.w;
    }
    __syncthreads();

    const int rt = t & 31;          // row tile 0..31
    const int ct = t >> 5;          // col tile 0..5
    const int r0 = rt * 8, c0 = ct * 8;

    unsigned long long acc2[8][4];
    {
        unsigned long long b0 = pack2(bes[c0 + 0], bes[c0 + 1]);
        unsigned long long b1 = pack2(bes[c0 + 2], bes[c0 + 3]);
        unsigned long long b2v = pack2(bes[c0 + 4], bes[c0 + 5]);
        unsigned long long b3 = pack2(bes[c0 + 6], bes[c0 + 7]);
        #pragma unroll
        for (int m = 0; m < 8; m++) {
            acc2[m][0] = b0; acc2[m][1] = b1; acc2[m][2] = b2v; acc2[m][3] = b3;
        }
    }

    #pragma unroll 8
    for (int k = 0; k < EDGE_F; k++) {
        int rs = r0 ^ (8 * ((k >> 2) & 3));
        float4 alo = *(const float4*)&AsT[k][rs];
        float4 ahi = *(const float4*)&AsT[k][rs + 4];
        ulonglong2 bA = *(const ulonglong2*)&Bs[k][c0];
        ulonglong2 bB = *(const ulonglong2*)&Bs[k][c0 + 4];
        unsigned long long bb0 = bA.x, bb1 = bA.y, bb2 = bB.x, bb3 = bB.y;
        float a[8] = {alo.x, alo.y, alo.z, alo.w, ahi.x, ahi.y, ahi.z, ahi.w};
        #pragma unroll
        for (int m = 0; m < 8; m++) {
            unsigned long long am = pack2(a[m], a[m]);
            acc2[m][0] = fma2(am, bb0, acc2[m][0]);
            acc2[m][1] = fma2(am, bb1, acc2[m][1]);
            acc2[m][2] = fma2(am, bb2, acc2[m][2]);
            acc2[m][3] = fma2(am, bb3, acc2[m][3]);
        }
    }

    // epilogue: relu, * nfeat[src], segment scan over 8 sorted rows, atomic flush
    float s0 = 0.f, s1 = 0.f, s2 = 0.f, s3 = 0.f, s4 = 0.f, s5 = 0.f, s6 = 0.f, s7 = 0.f;
    int cur = dsts_s[r0];
    #pragma unroll
    for (int i = 0; i < 8; i++) {
        int d = dsts_s[r0 + i];
        if (d != cur) {
            float* hp = &g_hsum[(size_t)cur * IN_F + c0];
            atomicAdd(hp + 0, s0); atomicAdd(hp + 1, s1);
            atomicAdd(hp + 2, s2); atomicAdd(hp + 3, s3);
            atomicAdd(hp + 4, s4); atomicAdd(hp + 5, s5);
            atomicAdd(hp + 6, s6); atomicAdd(hp + 7, s7);
            s0 = s1 = s2 = s3 = s4 = s5 = s6 = s7 = 0.f;
            cur = d;
        }
        const float* nf = &nfeat[(size_t)srcs_s[r0 + i] * IN_F + c0];
        float4 n0 = *(const float4*)nf;
        float4 n1 = *(const float4*)(nf + 4);
        float2 e0 = unpack2(acc2[i][0]);
        float2 e1 = unpack2(acc2[i][1]);
        float2 e2 = unpack2(acc2[i][2]);
        float2 e3 = unpack2(acc2[i][3]);
        s0 = fmaf(fmaxf(e0.x, 0.f), n0.x, s0);
        s1 = fmaf(fmaxf(e0.y, 0.f), n0.y, s1);
        s2 = fmaf(fmaxf(e1.x, 0.f), n0.z, s2);
        s3 = fmaf(fmaxf(e1.y, 0.f), n0.w, s3);
        s4 = fmaf(fmaxf(e2.x, 0.f), n1.x, s4);
        s5 = fmaf(fmaxf(e2.y, 0.f), n1.y, s5);
        s6 = fmaf(fmaxf(e3.x, 0.f), n1.z, s6);
        s7 = fmaf(fmaxf(e3.y, 0.f), n1.w, s7);
    }
    float* hp = &g_hsum[(size_t)cur * IN_F + c0];
    atomicAdd(hp + 0, s0); atomicAdd(hp + 1, s1);
    atomicAdd(hp + 2, s2); atomicAdd(hp + 3, s3);
    atomicAdd(hp + 4, s4); atomicAdd(hp + 5, s5);
    atomicAdd(hp + 6, s6); atomicAdd(hp + 7, s7);
}

// divide by degree + build concat h = [nfeat | mean]
__global__ void k_finalize0(const float* __restrict__ nfeat) {
    int i = blockIdx.x * blockDim.x + threadIdx.x;
    if (i >= N_NODES * IN_F) return;
    int n = i / IN_F, c = i % IN_F;
    int deg = g_rowptr[n + 1] - g_rowptr[n];
    float inv = 1.f / fmaxf((float)deg, 1.f);
    g_h[n * H0_F + c]        = nfeat[i];
    g_h[n * H0_F + IN_F + c] = g_hsum[i] * inv;
}

// ---------------- mean96: warp per node, unroll-2 dual accumulators ----------------
__global__ void __launch_bounds__(256) k_mean96() {
    int gw = (blockIdx.x * blockDim.x + threadIdx.x) >> 5;
    int l  = threadIdx.x & 31;
    if (gw >= N_NODES) return;
    int beg = g_rowptr[gw], end = g_rowptr[gw + 1];
    float a0 = 0.f, a1 = 0.f, a2 = 0.f, b0 = 0.f, b1 = 0.f, b2 = 0.f;
    int j = beg;
    for (; j + 2 <= end; j += 2) {
        const float* ra = &g_h[(size_t)g_csr_src[j]     * H0_F];
        const float* rb = &g_h[(size_t)g_csr_src[j + 1] * H0_F];
        a0 += __ldg(ra + l);      a1 += __ldg(ra + 32 + l); a2 += __ldg(ra + 64 + l);
        b0 += __ldg(rb + l);      b1 += __ldg(rb + 32 + l); b2 += __ldg(rb + 64 + l);
    }
    if (j < end) {
        const float* ra = &g_h[(size_t)g_csr_src[j] * H0_F];
        a0 += __ldg(ra + l); a1 += __ldg(ra + 32 + l); a2 += __ldg(ra + 64 + l);
    }
    float inv = 1.f / fmaxf((float)(end - beg), 1.f);
    float* o = &g_hn1[(size_t)gw * H0_F];
    o[l] = (a0 + b0) * inv; o[32 + l] = (a1 + b1) * inv; o[64 + l] = (a2 + b2) * inv;
}

// ---------------- GEMM1: g_h1 = relu(g_h@W1s + g_hn1@W1n + b1) ----------------
// 256 threads, BM=128, NOUT=128, 8x8 micro-tile, f32x2, transposed-A smem
__global__ void __launch_bounds__(256) k_gemm1(
    const float* __restrict__ Wa, const float* __restrict__ Wb,
    const float* __restrict__ bias)
{
    constexpr int BM = 128, BK = 32, NOUT = HID_F, APAD = BM + 4;
    __shared__ float AsT[BK][APAD];
    __shared__ float Bs[BK][NOUT];

    int t  = threadIdx.x;
    int tx = t & 15, ty = t >> 4;
    int brow = blockIdx.x * BM;
    int r0 = ty * 8, c0 = tx * 8;

    unsigned long long acc2[8][4];
    #pragma unroll
    for (int m = 0; m < 8; m++)
        #pragma unroll
        for (int j = 0; j < 4; j++) acc2[m][j] = pack2(0.f, 0.f);

    #pragma unroll
    for (int phase = 0; phase < 2; phase++) {
        const float* A = phase ? g_hn1 : g_h;
        const float* W = phase ? Wb : Wa;
        for (int kt = 0; kt < H0_F; kt += BK) {
            #pragma unroll
            for (int i = 0; i < 4; i++) {
                int idx = t + i * 256;
                int r = idx >> 3, c4 = idx & 7;
                int grow = brow + r;
                float4 v = make_float4(0.f, 0.f, 0.f, 0.f);
                if (grow < N_NODES)
                    v = *(const float4*)&A[(size_t)grow * H0_F + kt + c4 * 4];
                int pos = r ^ (8 * (c4 & 3));
                AsT[4 * c4 + 0][pos] = v.x;
                AsT[4 * c4 + 1][pos] = v.y;
                AsT[4 * c4 + 2][pos] = v.z;
                AsT[4 * c4 + 3][pos] = v.w;
            }
            #pragma unroll
            for (int i = 0; i < 4; i++) {
                int idx = t + i * 256;
                int r = idx >> 5, c4 = idx & 31;
                *(float4*)&Bs[r][c4 * 4] = *(const float4*)&W[(size_t)(kt + r) * NOUT + c4 * 4];
            }
            __syncthreads();
            #pragma unroll 8
            for (int k = 0; k < BK; k++) {
                int rs = r0 ^ (8 * ((k >> 2) & 3));
                float4 alo = *(const float4*)&AsT[k][rs];
                float4 ahi = *(const float4*)&AsT[k][rs + 4];
                ulonglong2 bA = *(const ulonglong2*)&Bs[k][c0];
                ulonglong2 bB = *(const ulonglong2*)&Bs[k][c0 + 4];
                unsigned long long bb0 = bA.x, bb1 = bA.y, bb2 = bB.x, bb3 = bB.y;
                float a[8] = {alo.x, alo.y, alo.z, alo.w, ahi.x, ahi.y, ahi.z, ahi.w};
                #pragma unroll
                for (int m = 0; m < 8; m++) {
                    unsigned long long am = pack2(a[m], a[m]);
                    acc2[m][0] = fma2(am, bb0, acc2[m][0]);
                    acc2[m][1] = fma2(am, bb1, acc2[m][1]);
                    acc2[m][2] = fma2(am, bb2, acc2[m][2]);
                    acc2[m][3] = fma2(am, bb3, acc2[m][3]);
                }
            }
            __syncthreads();
        }
    }
    #pragma unroll
    for (int m = 0; m < 8; m++) {
        int grow = brow + r0 + m;
        if (grow < N_NODES) {
            #pragma unroll
            for (int j = 0; j < 4; j++) {
                float2 c2 = unpack2(acc2[m][j]);
                float v0 = fmaxf(c2.x + bias[c0 + 2 * j],     0.f);
                float v1 = fmaxf(c2.y + bias[c0 + 2 * j + 1], 0.f);
                *(float2*)&g_h1[(size_t)grow * HID_F + c0 + 2 * j] = make_float2(v0, v1);
            }
        }
    }
}

// ---------------- GEMM2: g_s2z = [h1@W2s + b2 | h1@W2n] ----------------
__global__ void __launch_bounds__(256) k_gemm2(
    const float* __restrict__ Wa, const float* __restrict__ Wb,
    const float* __restrict__ bias)
{
    constexpr int BM = 128, BK = 32, NOUT = 128, APAD = BM + 4;
    __shared__ float AsT[BK][APAD];
    __shared__ float Bs[BK][NOUT];

    int t  = threadIdx.x;
    int tx = t & 15, ty = t >> 4;
    int brow = blockIdx.x * BM;
    int r0 = ty * 8, c0 = tx * 8;

    unsigned long long acc2[8][4];
    #pragma unroll
    for (int m = 0; m < 8; m++)
        #pragma unroll
        for (int j = 0; j < 4; j++) acc2[m][j] = pack2(0.f, 0.f);

    for (int kt = 0; kt < HID_F; kt += BK) {
        #pragma unroll
        for (int i = 0; i < 4; i++) {
            int idx = t + i * 256;
            int r = idx >> 3, c4 = idx & 7;
            int grow = brow + r;
            float4 v = make_float4(0.f, 0.f, 0.f, 0.f);
            if (grow < N_NODES)
                v = *(const float4*)&g_h1[(size_t)grow * HID_F + kt + c4 * 4];
            int pos = r ^ (8 * (c4 & 3));
            AsT[4 * c4 + 0][pos] = v.x;
            AsT[4 * c4 + 1][pos] = v.y;
            AsT[4 * c4 + 2][pos] = v.z;
            AsT[4 * c4 + 3][pos] = v.w;
        }
        #pragma unroll
        for (int i = 0; i < 4; i++) {
            int idx = t + i * 256;
            int r = idx >> 5, c4 = idx & 31;
            float4 v;
            if (c4 < 16) v = *(const float4*)&Wa[(size_t)(kt + r) * OUT_F + c4 * 4];
            else         v = *(const float4*)&Wb[(size_t)(kt + r) * OUT_F + (c4 - 16) * 4];
            *(float4*)&Bs[r][c4 * 4] = v;
        }
        __syncthreads();
        #pragma unroll 8
        for (int k = 0; k < BK; k++) {
            int rs = r0 ^ (8 * ((k >> 2) & 3));
            float4 alo = *(const float4*)&AsT[k][rs];
            float4 ahi = *(const float4*)&AsT[k][rs + 4];
            ulonglong2 bA = *(const ulonglong2*)&Bs[k][c0];
            ulonglong2 bB = *(const ulonglong2*)&Bs[k][c0 + 4];
            unsigned long long bb0 = bA.x, bb1 = bA.y, bb2 = bB.x, bb3 = bB.y;
            float a[8] = {alo.x, alo.y, alo.z, alo.w, ahi.x, ahi.y, ahi.z, ahi.w};
            #pragma unroll
            for (int m = 0; m < 8; m++) {
                unsigned long long am = pack2(a[m], a[m]);
                acc2[m][0] = fma2(am, bb0, acc2[m][0]);
                acc2[m][1] = fma2(am, bb1, acc2[m][1]);
                acc2[m][2] = fma2(am, bb2, acc2[m][2]);
                acc2[m][3] = fma2(am, bb3, acc2[m][3]);
            }
        }
        __syncthreads();
    }
    #pragma unroll
    for (int m = 0; m < 8; m++) {
        int grow = brow + r0 + m;
        if (grow < N_NODES) {
            #pragma unroll
            for (int j = 0; j < 4; j++) {
                int col = c0 + 2 * j;
                float2 c2 = unpack2(acc2[m][j]);
                float v0 = c2.x + (col     < OUT_F ? bias[col]     : 0.f);
                float v1 = c2.y + (col + 1 < OUT_F ? bias[col + 1] : 0.f);
                *(float2*)&g_s2z[(size_t)grow * 128 + col] = make_float2(v0, v1);
            }
        }
    }
}

// ---------------- final: out = S2 + seg_mean(Z[src]) ----------------
__global__ void __launch_bounds__(256) k_final(float* __restrict__ out) {
    int gw = (blockIdx.x * blockDim.x + threadIdx.x) >> 5;
    int l  = threadIdx.x & 31;
    if (gw >= N_NODES) return;
    int beg = g_rowptr[gw], end = g_rowptr[gw + 1];
    float a0 = 0.f, a1 = 0.f, b0 = 0.f, b1 = 0.f;
    int j = beg;
    for (; j + 2 <= end; j += 2) {
        const float* ra = &g_s2z[(size_t)g_csr_src[j]     * 128 + OUT_F];
        const float* rb = &g_s2z[(size_t)g_csr_src[j + 1] * 128 + OUT_F];
        a0 += __ldg(ra + l); a1 += __ldg(ra + 32 + l);
        b0 += __ldg(rb + l); b1 += __ldg(rb + 32 + l);
    }
    if (j < end) {
        const float* ra = &g_s2z[(size_t)g_csr_src[j] * 128 + OUT_F];
        a0 += __ldg(ra + l); a1 += __ldg(ra + 32 + l);
    }
    float inv = 1.f / fmaxf((float)(end - beg), 1.f);
    const float* s2 = &g_s2z[(size_t)gw * 128];
    out[(size_t)gw * OUT_F + l]      = s2[l]      + (a0 + b0) * inv;
    out[(size_t)gw * OUT_F + 32 + l] = s2[32 + l] + (a1 + b1) * inv;
}

// ---------------- launch ----------------
extern "C" void kernel_launch(void* const* d_in, const int* in_sizes, int n_in,
                              void* d_out, int out_size)
{
    const float* nfeat = (const float*)d_in[0];
    const float* efeat = (const float*)d_in[1];
    const int*   src   = (const int*)d_in[2];
    const int*   dst   = (const int*)d_in[3];
    const float* We    = (const float*)d_in[4];
    const float* be    = (const float*)d_in[5];
    const float* W1s   = (const float*)d_in[6];
    const float* W1n   = (const float*)d_in[7];
    const float* b1    = (const float*)d_in[8];
    const float* W2s   = (const float*)d_in[9];
    const float* W2n   = (const float*)d_in[10];
    const float* b2    = (const float*)d_in[11];
    float* out = (float*)d_out;

    const int WARP_GRID = (N_NODES * 32 + 255) / 256;

    void* p = nullptr;
    cudaGetSymbolAddress(&p, g_deg);
    cudaMemsetAsync(p, 0, N_NODES * sizeof(int));
    cudaGetSymbolAddress(&p, g_hsum);
    cudaMemsetAsync(p, 0, (size_t)N_NODES * IN_F * sizeof(float));

    k_deg<<<(N_EDGES + 255) / 256, 256>>>(dst);
    k_scan<<<1, 1024>>>();
    k_fill<<<(N_EDGES + 255) / 256, 256>>>(src, dst);
    k_layer0_gemm<<<N_EDGES / L0_TILE, L0_THREADS>>>(nfeat, efeat, We, be);
    k_finalize0<<<(N_NODES * IN_F + 255) / 256, 256>>>(nfeat);
    k_mean96<<<WARP_GRID, 256>>>();
    k_gemm1<<<(N_NODES + 127) / 128, 256>>>(W1s, W1n, b1);
    k_gemm2<<<(N_NODES + 127) / 128, 256>>>(W2s, W2n, b2);
    k_final<<<WARP_GRID, 256>>>(out);
}

// round 9
// speedup vs baseline: 1.6355x; 1.0756x over previous
#include <cuda_runtime.h>

#define N_NODES 100000
#define N_EDGES 1600000
#define IN_F    48
#define EDGE_F  32
#define HID_F   128
#define OUT_F   64
#define H0_F    96   // 2*IN_F

// ---------------- scratch (static device allocations only) ----------------
__device__ int   g_deg[N_NODES];
__device__ int   g_rowptr[N_NODES + 1];
__device__ int   g_cursor[N_NODES];
__device__ int   g_csr_src[N_EDGES];
__device__ int   g_csr_eid[N_EDGES];
__device__ int   g_csr_dst[N_EDGES];
__device__ float g_hsum[N_NODES * IN_F];   // layer0 aggregated sums (pre-mean)
__device__ float g_h  [N_NODES * H0_F];    // concat(nfeat, h_neigh0)
__device__ float g_hn1[N_NODES * H0_F];    // seg_mean(h[src])
__device__ float g_h1 [N_NODES * HID_F];   // layer1 output
__device__ float g_s2z[N_NODES * 128];     // [h1@W2s+b2 | h1@W2n]

// ---------------- packed f32x2 helpers ----------------
__device__ __forceinline__ unsigned long long pack2(float lo, float hi) {
    unsigned long long u;
    asm("mov.b64 %0, {%1, %2};" : "=l"(u) : "f"(lo), "f"(hi));
    return u;
}
__device__ __forceinline__ float2 unpack2(unsigned long long u) {
    float lo, hi;
    asm("mov.b64 {%0, %1}, %2;" : "=f"(lo), "=f"(hi) : "l"(u));
    return make_float2(lo, hi);
}
__device__ __forceinline__ unsigned long long fma2(unsigned long long a,
                                                   unsigned long long b,
                                                   unsigned long long c) {
    unsigned long long d;
    asm("fma.rn.f32x2 %0, %1, %2, %3;" : "=l"(d) : "l"(a), "l"(b), "l"(c));
    return d;
}

// ---------------- CSR build ----------------
__global__ void k_deg(const int* __restrict__ dst) {
    int i = blockIdx.x * blockDim.x + threadIdx.x;
    if (i < N_EDGES) atomicAdd(&g_deg[dst[i]], 1);
}

__global__ void k_scan() {
    __shared__ int wsum[32];
    __shared__ int running;
    int t = threadIdx.x, lane = t & 31, w = t >> 5;
    if (t == 0) running = 0;
    __syncthreads();
    for (int base = 0; base < N_NODES; base += 1024) {
        int i = base + t;
        int v = (i < N_NODES) ? g_deg[i] : 0;
        int x = v;
        #pragma unroll
        for (int o = 1; o < 32; o <<= 1) {
            int y = __shfl_up_sync(0xffffffffu, x, o);
            if (lane >= o) x += y;
        }
        if (lane == 31) wsum[w] = x;
        __syncthreads();
        if (w == 0) {
            int s = wsum[lane];
            #pragma unroll
            for (int o = 1; o < 32; o <<= 1) {
                int y = __shfl_up_sync(0xffffffffu, s, o);
                if (lane >= o) s += y;
            }
            wsum[lane] = s;
        }
        __syncthreads();
        int excl = running + (w ? wsum[w - 1] : 0) + (x - v);
        if (i < N_NODES) { g_rowptr[i] = excl; g_cursor[i] = excl; }
        __syncthreads();
        if (t == 0) running += wsum[31];
        __syncthreads();
    }
    if (t == 0) g_rowptr[N_NODES] = running;
}

__global__ void k_fill(const int* __restrict__ src, const int* __restrict__ dst) {
    int i = blockIdx.x * blockDim.x + threadIdx.x;
    if (i < N_EDGES) {
        int d = dst[i];
        int p = atomicAdd(&g_cursor[d], 1);
        g_csr_src[p] = src[i];
        g_csr_eid[p] = i;
        g_csr_dst[p] = d;
    }
}

// ---------------- layer0: register-tiled edge GEMM + segment reduce ----------------
// Block = 256 CSR slots. 384 threads: 64 row-tiles(4 rows) x 6 col-tiles(8 cols).
// E = relu(efeat@We + be); m = E * nfeat[src]; atomic segment-sum into g_hsum.
#define L0_TILE    256
#define L0_THREADS 384

__global__ void __launch_bounds__(L0_THREADS, 2) k_layer0_gemm(
    const float* __restrict__ nfeat, const float* __restrict__ efeat,
    const float* __restrict__ We, const float* __restrict__ be)
{
    __shared__ float AsT[EDGE_F][L0_TILE];   // k-major efeat tile, XOR swizzled
    __shared__ float Bs[EDGE_F][IN_F];       // 32x48 weights
    __shared__ float bes[IN_F];
    __shared__ int   srcs_s[L0_TILE];
    __shared__ int   dsts_s[L0_TILE];
    __shared__ int   eids_s[L0_TILE];

    const int t  = threadIdx.x;
    const int j0 = blockIdx.x * L0_TILE;

    for (int idx = t; idx < L0_TILE; idx += L0_THREADS) {
        srcs_s[idx] = g_csr_src[j0 + idx];
        dsts_s[idx] = g_csr_dst[j0 + idx];
        eids_s[idx] = g_csr_eid[j0 + idx];
    }
    // weights: 32x48 floats = 384 float4s, one per thread
    {
        int r = t / 12, c4 = t % 12;
        *(float4*)&Bs[r][c4 * 4] = *(const float4*)&We[r * IN_F + c4 * 4];
    }
    if (t < IN_F) bes[t] = be[t];
    __syncthreads();

    // gather efeat rows -> AsT (k-major, swizzled: pos = row ^ (8*(c4&3)))
    for (int idx = t; idx < L0_TILE * 8; idx += L0_THREADS) {
        int row = idx >> 3, c4 = idx & 7;
        float4 v = *(const float4*)&efeat[(size_t)eids_s[row] * EDGE_F + c4 * 4];
        int pos = row ^ (8 * (c4 & 3));
        AsT[4 * c4 + 0][pos] = v.x;
        AsT[4 * c4 + 1][pos] = v.y;
        AsT[4 * c4 + 2][pos] = v.z;
        AsT[4 * c4 + 3][pos] = v.w;
    }
    __syncthreads();

    const int rt = t & 63;          // row tile 0..63 (4 rows each)
    const int ct = t / 64;          // col tile 0..5 (8 cols each)
    const int r0 = rt * 4, c0 = ct * 8;

    unsigned long long acc2[4][4];
    {
        unsigned long long b0 = pack2(bes[c0 + 0], bes[c0 + 1]);
        unsigned long long b1 = pack2(bes[c0 + 2], bes[c0 + 3]);
        unsigned long long b2v = pack2(bes[c0 + 4], bes[c0 + 5]);
        unsigned long long b3 = pack2(bes[c0 + 6], bes[c0 + 7]);
        #pragma unroll
        for (int m = 0; m < 4; m++) {
            acc2[m][0] = b0; acc2[m][1] = b1; acc2[m][2] = b2v; acc2[m][3] = b3;
        }
    }

    #pragma unroll 8
    for (int k = 0; k < EDGE_F; k++) {
        int rs = r0 ^ (8 * ((k >> 2) & 3));
        float4 av = *(const float4*)&AsT[k][rs];
        ulonglong2 bA = *(const ulonglong2*)&Bs[k][c0];
        ulonglong2 bB = *(const ulonglong2*)&Bs[k][c0 + 4];
        unsigned long long bb0 = bA.x, bb1 = bA.y, bb2 = bB.x, bb3 = bB.y;
        float a[4] = {av.x, av.y, av.z, av.w};
        #pragma unroll
        for (int m = 0; m < 4; m++) {
            unsigned long long am = pack2(a[m], a[m]);
            acc2[m][0] = fma2(am, bb0, acc2[m][0]);
            acc2[m][1] = fma2(am, bb1, acc2[m][1]);
            acc2[m][2] = fma2(am, bb2, acc2[m][2]);
            acc2[m][3] = fma2(am, bb3, acc2[m][3]);
        }
    }

    // epilogue: batch all nfeat gathers first (8 independent LDG.128),
    // then relu * nfeat, serial segment scan over 4 sorted rows, atomic flush
    float4 nf0[4], nf1[4];
    #pragma unroll
    for (int i = 0; i < 4; i++) {
        const float* nf = &nfeat[(size_t)srcs_s[r0 + i] * IN_F + c0];
        nf0[i] = *(const float4*)nf;
        nf1[i] = *(const float4*)(nf + 4);
    }

    float s0 = 0.f, s1 = 0.f, s2 = 0.f, s3 = 0.f, s4 = 0.f, s5 = 0.f, s6 = 0.f, s7 = 0.f;
    int cur = dsts_s[r0];
    #pragma unroll
    for (int i = 0; i < 4; i++) {
        int d = dsts_s[r0 + i];
        if (d != cur) {
            float* hp = &g_hsum[(size_t)cur * IN_F + c0];
            atomicAdd(hp + 0, s0); atomicAdd(hp + 1, s1);
            atomicAdd(hp + 2, s2); atomicAdd(hp + 3, s3);
            atomicAdd(hp + 4, s4); atomicAdd(hp + 5, s5);
            atomicAdd(hp + 6, s6); atomicAdd(hp + 7, s7);
            s0 = s1 = s2 = s3 = s4 = s5 = s6 = s7 = 0.f;
            cur = d;
        }
        float2 e0 = unpack2(acc2[i][0]);
        float2 e1 = unpack2(acc2[i][1]);
        float2 e2 = unpack2(acc2[i][2]);
        float2 e3 = unpack2(acc2[i][3]);
        s0 = fmaf(fmaxf(e0.x, 0.f), nf0[i].x, s0);
        s1 = fmaf(fmaxf(e0.y, 0.f), nf0[i].y, s1);
        s2 = fmaf(fmaxf(e1.x, 0.f), nf0[i].z, s2);
        s3 = fmaf(fmaxf(e1.y, 0.f), nf0[i].w, s3);
        s4 = fmaf(fmaxf(e2.x, 0.f), nf1[i].x, s4);
        s5 = fmaf(fmaxf(e2.y, 0.f), nf1[i].y, s5);
        s6 = fmaf(fmaxf(e3.x, 0.f), nf1[i].z, s6);
        s7 = fmaf(fmaxf(e3.y, 0.f), nf1[i].w, s7);
    }
    float* hp = &g_hsum[(size_t)cur * IN_F + c0];
    atomicAdd(hp + 0, s0); atomicAdd(hp + 1, s1);
    atomicAdd(hp + 2, s2); atomicAdd(hp + 3, s3);
    atomicAdd(hp + 4, s4); atomicAdd(hp + 5, s5);
    atomicAdd(hp + 6, s6); atomicAdd(hp + 7, s7);
}

// divide by degree + build concat h = [nfeat | mean]
__global__ void k_finalize0(const float* __restrict__ nfeat) {
    int i = blockIdx.x * blockDim.x + threadIdx.x;
    if (i >= N_NODES * IN_F) return;
    int n = i / IN_F, c = i % IN_F;
    int deg = g_rowptr[n + 1] - g_rowptr[n];
    float inv = 1.f / fmaxf((float)deg, 1.f);
    g_h[n * H0_F + c]        = nfeat[i];
    g_h[n * H0_F + IN_F + c] = g_hsum[i] * inv;
}

// ---------------- mean96: warp per node, unroll-2 dual accumulators ----------------
__global__ void __launch_bounds__(256) k_mean96() {
    int gw = (blockIdx.x * blockDim.x + threadIdx.x) >> 5;
    int l  = threadIdx.x & 31;
    if (gw >= N_NODES) return;
    int beg = g_rowptr[gw], end = g_rowptr[gw + 1];
    float a0 = 0.f, a1 = 0.f, a2 = 0.f, b0 = 0.f, b1 = 0.f, b2 = 0.f;
    int j = beg;
    for (; j + 2 <= end; j += 2) {
        const float* ra = &g_h[(size_t)g_csr_src[j]     * H0_F];
        const float* rb = &g_h[(size_t)g_csr_src[j + 1] * H0_F];
        a0 += __ldg(ra + l);      a1 += __ldg(ra + 32 + l); a2 += __ldg(ra + 64 + l);
        b0 += __ldg(rb + l);      b1 += __ldg(rb + 32 + l); b2 += __ldg(rb + 64 + l);
    }
    if (j < end) {
        const float* ra = &g_h[(size_t)g_csr_src[j] * H0_F];
        a0 += __ldg(ra + l); a1 += __ldg(ra + 32 + l); a2 += __ldg(ra + 64 + l);
    }
    float inv = 1.f / fmaxf((float)(end - beg), 1.f);
    float* o = &g_hn1[(size_t)gw * H0_F];
    o[l] = (a0 + b0) * inv; o[32 + l] = (a1 + b1) * inv; o[64 + l] = (a2 + b2) * inv;
}

// ---------------- GEMM1: g_h1 = relu(g_h@W1s + g_hn1@W1n + b1) ----------------
__global__ void __launch_bounds__(256) k_gemm1(
    const float* __restrict__ Wa, const float* __restrict__ Wb,
    const float* __restrict__ bias)
{
    constexpr int BM = 128, BK = 32, NOUT = HID_F, APAD = BM + 4;
    __shared__ float AsT[BK][APAD];
    __shared__ float Bs[BK][NOUT];

    int t  = threadIdx.x;
    int tx = t & 15, ty = t >> 4;
    int brow = blockIdx.x * BM;
    int r0 = ty * 8, c0 = tx * 8;

    unsigned long long acc2[8][4];
    #pragma unroll
    for (int m = 0; m < 8; m++)
        #pragma unroll
        for (int j = 0; j < 4; j++) acc2[m][j] = pack2(0.f, 0.f);

    #pragma unroll
    for (int phase = 0; phase < 2; phase++) {
        const float* A = phase ? g_hn1 : g_h;
        const float* W = phase ? Wb : Wa;
        for (int kt = 0; kt < H0_F; kt += BK) {
            #pragma unroll
            for (int i = 0; i < 4; i++) {
                int idx = t + i * 256;
                int r = idx >> 3, c4 = idx & 7;
                int grow = brow + r;
                float4 v = make_float4(0.f, 0.f, 0.f, 0.f);
                if (grow < N_NODES)
                    v = *(const float4*)&A[(size_t)grow * H0_F + kt + c4 * 4];
                int pos = r ^ (8 * (c4 & 3));
                AsT[4 * c4 + 0][pos] = v.x;
                AsT[4 * c4 + 1][pos] = v.y;
                AsT[4 * c4 + 2][pos] = v.z;
                AsT[4 * c4 + 3][pos] = v.w;
            }
            #pragma unroll
            for (int i = 0; i < 4; i++) {
                int idx = t + i * 256;
                int r = idx >> 5, c4 = idx & 31;
                *(float4*)&Bs[r][c4 * 4] = *(const float4*)&W[(size_t)(kt + r) * NOUT + c4 * 4];
            }
            __syncthreads();
            #pragma unroll 8
            for (int k = 0; k < BK; k++) {
                int rs = r0 ^ (8 * ((k >> 2) & 3));
                float4 alo = *(const float4*)&AsT[k][rs];
                float4 ahi = *(const float4*)&AsT[k][rs + 4];
                ulonglong2 bA = *(const ulonglong2*)&Bs[k][c0];
                ulonglong2 bB = *(const ulonglong2*)&Bs[k][c0 + 4];
                unsigned long long bb0 = bA.x, bb1 = bA.y, bb2 = bB.x, bb3 = bB.y;
                float a[8] = {alo.x, alo.y, alo.z, alo.w, ahi.x, ahi.y, ahi.z, ahi.w};
                #pragma unroll
                for (int m = 0; m < 8; m++) {
                    unsigned long long am = pack2(a[m], a[m]);
                    acc2[m][0] = fma2(am, bb0, acc2[m][0]);
                    acc2[m][1] = fma2(am, bb1, acc2[m][1]);
                    acc2[m][2] = fma2(am, bb2, acc2[m][2]);
                    acc2[m][3] = fma2(am, bb3, acc2[m][3]);
                }
            }
            __syncthreads();
        }
    }
    #pragma unroll
    for (int m = 0; m < 8; m++) {
        int grow = brow + r0 + m;
        if (grow < N_NODES) {
            #pragma unroll
            for (int j = 0; j < 4; j++) {
                float2 c2 = unpack2(acc2[m][j]);
                float v0 = fmaxf(c2.x + bias[c0 + 2 * j],     0.f);
                float v1 = fmaxf(c2.y + bias[c0 + 2 * j + 1], 0.f);
                *(float2*)&g_h1[(size_t)grow * HID_F + c0 + 2 * j] = make_float2(v0, v1);
            }
        }
    }
}

// ---------------- GEMM2: g_s2z = [h1@W2s + b2 | h1@W2n] ----------------
__global__ void __launch_bounds__(256) k_gemm2(
    const float* __restrict__ Wa, const float* __restrict__ Wb,
    const float* __restrict__ bias)
{
    constexpr int BM = 128, BK = 32, NOUT = 128, APAD = BM + 4;
    __shared__ float AsT[BK][APAD];
    __shared__ float Bs[BK][NOUT];

    int t  = threadIdx.x;
    int tx = t & 15, ty = t >> 4;
    int brow = blockIdx.x * BM;
    int r0 = ty * 8, c0 = tx * 8;

    unsigned long long acc2[8][4];
    #pragma unroll
    for (int m = 0; m < 8; m++)
        #pragma unroll
        for (int j = 0; j < 4; j++) acc2[m][j] = pack2(0.f, 0.f);

    for (int kt = 0; kt < HID_F; kt += BK) {
        #pragma unroll
        for (int i = 0; i < 4; i++) {
            int idx = t + i * 256;
            int r = idx >> 3, c4 = idx & 7;
            int grow = brow + r;
            float4 v = make_float4(0.f, 0.f, 0.f, 0.f);
            if (grow < N_NODES)
                v = *(const float4*)&g_h1[(size_t)grow * HID_F + kt + c4 * 4];
            int pos = r ^ (8 * (c4 & 3));
            AsT[4 * c4 + 0][pos] = v.x;
            AsT[4 * c4 + 1][pos] = v.y;
            AsT[4 * c4 + 2][pos] = v.z;
            AsT[4 * c4 + 3][pos] = v.w;
        }
        #pragma unroll
        for (int i = 0; i < 4; i++) {
            int idx = t + i * 256;
            int r = idx >> 5, c4 = idx & 31;
            float4 v;
            if (c4 < 16) v = *(const float4*)&Wa[(size_t)(kt + r) * OUT_F + c4 * 4];
            else         v = *(const float4*)&Wb[(size_t)(kt + r) * OUT_F + (c4 - 16) * 4];
            *(float4*)&Bs[r][c4 * 4] = v;
        }
        __syncthreads();
        #pragma unroll 8
        for (int k = 0; k < BK; k++) {
            int rs = r0 ^ (8 * ((k >> 2) & 3));
            float4 alo = *(const float4*)&AsT[k][rs];
            float4 ahi = *(const float4*)&AsT[k][rs + 4];
            ulonglong2 bA = *(const ulonglong2*)&Bs[k][c0];
            ulonglong2 bB = *(const ulonglong2*)&Bs[k][c0 + 4];
            unsigned long long bb0 = bA.x, bb1 = bA.y, bb2 = bB.x, bb3 = bB.y;
            float a[8] = {alo.x, alo.y, alo.z, alo.w, ahi.x, ahi.y, ahi.z, ahi.w};
            #pragma unroll
            for (int m = 0; m < 8; m++) {
                unsigned long long am = pack2(a[m], a[m]);
                acc2[m][0] = fma2(am, bb0, acc2[m][0]);
                acc2[m][1] = fma2(am, bb1, acc2[m][1]);
                acc2[m][2] = fma2(am, bb2, acc2[m][2]);
                acc2[m][3] = fma2(am, bb3, acc2[m][3]);
            }
        }
        __syncthreads();
    }
    #pragma unroll
    for (int m = 0; m < 8; m++) {
        int grow = brow + r0 + m;
        if (grow < N_NODES) {
            #pragma unroll
            for (int j = 0; j < 4; j++) {
                int col = c0 + 2 * j;
                float2 c2 = unpack2(acc2[m][j]);
                float v0 = c2.x + (col     < OUT_F ? bias[col]     : 0.f);
                float v1 = c2.y + (col + 1 < OUT_F ? bias[col + 1] : 0.f);
                *(float2*)&g_s2z[(size_t)grow * 128 + col] = make_float2(v0, v1);
            }
        }
    }
}

// ---------------- final: out = S2 + seg_mean(Z[src]) ----------------
__global__ void __launch_bounds__(256) k_final(float* __restrict__ out) {
    int gw = (blockIdx.x * blockDim.x + threadIdx.x) >> 5;
    int l  = threadIdx.x & 31;
    if (gw >= N_NODES) return;
    int beg = g_rowptr[gw], end = g_rowptr[gw + 1];
    float a0 = 0.f, a1 = 0.f, b0 = 0.f, b1 = 0.f;
    int j = beg;
    for (; j + 2 <= end; j += 2) {
        const float* ra = &g_s2z[(size_t)g_csr_src[j]     * 128 + OUT_F];
        const float* rb = &g_s2z[(size_t)g_csr_src[j + 1] * 128 + OUT_F];
        a0 += __ldg(ra + l); a1 += __ldg(ra + 32 + l);
        b0 += __ldg(rb + l); b1 += __ldg(rb + 32 + l);
    }
    if (j < end) {
        const float* ra = &g_s2z[(size_t)g_csr_src[j] * 128 + OUT_F];
        a0 += __ldg(ra + l); a1 += __ldg(ra + 32 + l);
    }
    float inv = 1.f / fmaxf((float)(end - beg), 1.f);
    const float* s2 = &g_s2z[(size_t)gw * 128];
    out[(size_t)gw * OUT_F + l]      = s2[l]      + (a0 + b0) * inv;
    out[(size_t)gw * OUT_F + 32 + l] = s2[32 + l] + (a1 + b1) * inv;
}

// ---------------- launch ----------------
extern "C" void kernel_launch(void* const* d_in, const int* in_sizes, int n_in,
                              void* d_out, int out_size)
{
    const float* nfeat = (const float*)d_in[0];
    const float* efeat = (const float*)d_in[1];
    const int*   src   = (const int*)d_in[2];
    const int*   dst   = (const int*)d_in[3];
    const float* We    = (const float*)d_in[4];
    const float* be    = (const float*)d_in[5];
    const float* W1s   = (const float*)d_in[6];
    const float* W1n   = (const float*)d_in[7];
    const float* b1    = (const float*)d_in[8];
    const float* W2s   = (const float*)d_in[9];
    const float* W2n   = (const float*)d_in[10];
    const float* b2    = (const float*)d_in[11];
    float* out = (float*)d_out;

    const int WARP_GRID = (N_NODES * 32 + 255) / 256;

    void* p = nullptr;
    cudaGetSymbolAddress(&p, g_deg);
    cudaMemsetAsync(p, 0, N_NODES * sizeof(int));
    cudaGetSymbolAddress(&p, g_hsum);
    cudaMemsetAsync(p, 0, (size_t)N_NODES * IN_F * sizeof(float));

    k_deg<<<(N_EDGES + 255) / 256, 256>>>(dst);
    k_scan<<<1, 1024>>>();
    k_fill<<<(N_EDGES + 255) / 256, 256>>>(src, dst);
    k_layer0_gemm<<<N_EDGES / L0_TILE, L0_THREADS>>>(nfeat, efeat, We, be);
    k_finalize0<<<(N_NODES * IN_F + 255) / 256, 256>>>(nfeat);
    k_mean96<<<WARP_GRID, 256>>>();
    k_gemm1<<<(N_NODES + 127) / 128, 256>>>(W1s, W1n, b1);
    k_gemm2<<<(N_NODES + 127) / 128, 256>>>(W2s, W2n, b2);
    k_final<<<WARP_GRID, 256>>>(out);
}

// round 10
// speedup vs baseline: 1.7989x; 1.0999x over previous
#include <cuda_runtime.h>

#define N_NODES 100000
#define N_EDGES 1600000
#define IN_F    48
#define EDGE_F  32
#define HID_F   128
#define OUT_F   64
#define H0_F    96   // 2*IN_F

// ---------------- scratch (static device allocations only) ----------------
__device__ int   g_deg[N_NODES];
__device__ int   g_rowptr[N_NODES + 1];
__device__ int   g_cursor[N_NODES];
__device__ int4  g_csr[N_EDGES];           // (src, eid, dst, pad) packed
__device__ float g_hsum[N_NODES * IN_F];   // layer0 aggregated sums (pre-mean)
__device__ float g_h  [N_NODES * H0_F];    // concat(nfeat, h_neigh0)
__device__ float g_hn1[N_NODES * H0_F];    // seg_mean(h[src])
__device__ float g_h1 [N_NODES * HID_F];   // layer1 output
__device__ float g_s2z[N_NODES * 128];     // [h1@W2s+b2 | h1@W2n]

// ---------------- packed f32x2 helpers ----------------
__device__ __forceinline__ unsigned long long pack2(float lo, float hi) {
    unsigned long long u;
    asm("mov.b64 %0, {%1, %2};" : "=l"(u) : "f"(lo), "f"(hi));
    return u;
}
__device__ __forceinline__ float2 unpack2(unsigned long long u) {
    float lo, hi;
    asm("mov.b64 {%0, %1}, %2;" : "=f"(lo), "=f"(hi) : "l"(u));
    return make_float2(lo, hi);
}
__device__ __forceinline__ unsigned long long fma2(unsigned long long a,
                                                   unsigned long long b,
                                                   unsigned long long c) {
    unsigned long long d;
    asm("fma.rn.f32x2 %0, %1, %2, %3;" : "=l"(d) : "l"(a), "l"(b), "l"(c));
    return d;
}
// vector reduction: 4 floats in one red op (sm_90+)
__device__ __forceinline__ void red_add_v4(float* p, float a, float b, float c, float d) {
    asm volatile("red.global.add.v4.f32 [%0], {%1, %2, %3, %4};"
                 :: "l"(p), "f"(a), "f"(b), "f"(c), "f"(d) : "memory");
}

// ---------------- CSR build ----------------
__global__ void k_deg(const int* __restrict__ dst) {
    int i = blockIdx.x * blockDim.x + threadIdx.x;
    if (i < N_EDGES) atomicAdd(&g_deg[dst[i]], 1);
}

__global__ void k_scan() {
    __shared__ int wsum[32];
    __shared__ int running;
    int t = threadIdx.x, lane = t & 31, w = t >> 5;
    if (t == 0) running = 0;
    __syncthreads();
    for (int base = 0; base < N_NODES; base += 1024) {
        int i = base + t;
        int v = (i < N_NODES) ? g_deg[i] : 0;
        int x = v;
        #pragma unroll
        for (int o = 1; o < 32; o <<= 1) {
            int y = __shfl_up_sync(0xffffffffu, x, o);
            if (lane >= o) x += y;
        }
        if (lane == 31) wsum[w] = x;
        __syncthreads();
        if (w == 0) {
            int s = wsum[lane];
            #pragma unroll
            for (int o = 1; o < 32; o <<= 1) {
                int y = __shfl_up_sync(0xffffffffu, s, o);
                if (lane >= o) s += y;
            }
            wsum[lane] = s;
        }
        __syncthreads();
        int excl = running + (w ? wsum[w - 1] : 0) + (x - v);
        if (i < N_NODES) { g_rowptr[i] = excl; g_cursor[i] = excl; }
        __syncthreads();
        if (t == 0) running += wsum[31];
        __syncthreads();
    }
    if (t == 0) g_rowptr[N_NODES] = running;
}

__global__ void k_fill(const int* __restrict__ src, const int* __restrict__ dst) {
    int i = blockIdx.x * blockDim.x + threadIdx.x;
    if (i < N_EDGES) {
        int d = dst[i];
        int p = atomicAdd(&g_cursor[d], 1);
        g_csr[p] = make_int4(src[i], i, d, 0);
    }
}

// ---------------- layer0: register-tiled edge GEMM + segment reduce ----------------
// Block = 256 CSR slots. 384 threads: 64 row-tiles(4 rows) x 6 col-tiles(8 cols).
// E = relu(efeat@We + be); m = E * nfeat[src]; vector-red segment-sum into g_hsum.
#define L0_TILE    256
#define L0_THREADS 384

__global__ void __launch_bounds__(L0_THREADS, 2) k_layer0_gemm(
    const float* __restrict__ nfeat, const float* __restrict__ efeat,
    const float* __restrict__ We, const float* __restrict__ be)
{
    __shared__ float AsT[EDGE_F][L0_TILE];   // k-major efeat tile, XOR swizzled
    __shared__ float Bs[EDGE_F][IN_F];       // 32x48 weights
    __shared__ float bes[IN_F];
    __shared__ int   srcs_s[L0_TILE];
    __shared__ int   dsts_s[L0_TILE];
    __shared__ int   eids_s[L0_TILE];

    const int t  = threadIdx.x;
    const int j0 = blockIdx.x * L0_TILE;

    for (int idx = t; idx < L0_TILE; idx += L0_THREADS) {
        int4 v = g_csr[j0 + idx];
        srcs_s[idx] = v.x;
        eids_s[idx] = v.y;
        dsts_s[idx] = v.z;
    }
    // weights: 32x48 floats = 384 float4s, one per thread
    {
        int r = t / 12, c4 = t % 12;
        *(float4*)&Bs[r][c4 * 4] = *(const float4*)&We[r * IN_F + c4 * 4];
    }
    if (t < IN_F) bes[t] = be[t];
    __syncthreads();

    // gather efeat rows -> AsT (k-major, swizzled: pos = row ^ (8*(c4&3)))
    for (int idx = t; idx < L0_TILE * 8; idx += L0_THREADS) {
        int row = idx >> 3, c4 = idx & 7;
        float4 v = *(const float4*)&efeat[(size_t)eids_s[row] * EDGE_F + c4 * 4];
        int pos = row ^ (8 * (c4 & 3));
        AsT[4 * c4 + 0][pos] = v.x;
        AsT[4 * c4 + 1][pos] = v.y;
        AsT[4 * c4 + 2][pos] = v.z;
        AsT[4 * c4 + 3][pos] = v.w;
    }
    __syncthreads();

    const int rt = t & 63;          // row tile 0..63 (4 rows each)
    const int ct = t / 64;          // col tile 0..5 (8 cols each)
    const int r0 = rt * 4, c0 = ct * 8;

    unsigned long long acc2[4][4];
    {
        unsigned long long b0 = pack2(bes[c0 + 0], bes[c0 + 1]);
        unsigned long long b1 = pack2(bes[c0 + 2], bes[c0 + 3]);
        unsigned long long b2v = pack2(bes[c0 + 4], bes[c0 + 5]);
        unsigned long long b3 = pack2(bes[c0 + 6], bes[c0 + 7]);
        #pragma unroll
        for (int m = 0; m < 4; m++) {
            acc2[m][0] = b0; acc2[m][1] = b1; acc2[m][2] = b2v; acc2[m][3] = b3;
        }
    }

    #pragma unroll 8
    for (int k = 0; k < EDGE_F; k++) {
        int rs = r0 ^ (8 * ((k >> 2) & 3));
        float4 av = *(const float4*)&AsT[k][rs];
        ulonglong2 bA = *(const ulonglong2*)&Bs[k][c0];
        ulonglong2 bB = *(const ulonglong2*)&Bs[k][c0 + 4];
        unsigned long long bb0 = bA.x, bb1 = bA.y, bb2 = bB.x, bb3 = bB.y;
        float a[4] = {av.x, av.y, av.z, av.w};
        #pragma unroll
        for (int m = 0; m < 4; m++) {
            unsigned long long am = pack2(a[m], a[m]);
            acc2[m][0] = fma2(am, bb0, acc2[m][0]);
            acc2[m][1] = fma2(am, bb1, acc2[m][1]);
            acc2[m][2] = fma2(am, bb2, acc2[m][2]);
            acc2[m][3] = fma2(am, bb3, acc2[m][3]);
        }
    }

    // epilogue: batch all nfeat gathers first (8 independent LDG.128),
    // then relu * nfeat, serial segment scan over 4 sorted rows, vector-red flush
    float4 nf0[4], nf1[4];
    #pragma unroll
    for (int i = 0; i < 4; i++) {
        const float* nf = &nfeat[(size_t)srcs_s[r0 + i] * IN_F + c0];
        nf0[i] = *(const float4*)nf;
        nf1[i] = *(const float4*)(nf + 4);
    }

    float s0 = 0.f, s1 = 0.f, s2 = 0.f, s3 = 0.f, s4 = 0.f, s5 = 0.f, s6 = 0.f, s7 = 0.f;
    int cur = dsts_s[r0];
    #pragma unroll
    for (int i = 0; i < 4; i++) {
        int d = dsts_s[r0 + i];
        if (d != cur) {
            float* hp = &g_hsum[(size_t)cur * IN_F + c0];
            red_add_v4(hp,     s0, s1, s2, s3);
            red_add_v4(hp + 4, s4, s5, s6, s7);
            s0 = s1 = s2 = s3 = s4 = s5 = s6 = s7 = 0.f;
            cur = d;
        }
        float2 e0 = unpack2(acc2[i][0]);
        float2 e1 = unpack2(acc2[i][1]);
        float2 e2 = unpack2(acc2[i][2]);
        float2 e3 = unpack2(acc2[i][3]);
        s0 = fmaf(fmaxf(e0.x, 0.f), nf0[i].x, s0);
        s1 = fmaf(fmaxf(e0.y, 0.f), nf0[i].y, s1);
        s2 = fmaf(fmaxf(e1.x, 0.f), nf0[i].z, s2);
        s3 = fmaf(fmaxf(e1.y, 0.f), nf0[i].w, s3);
        s4 = fmaf(fmaxf(e2.x, 0.f), nf1[i].x, s4);
        s5 = fmaf(fmaxf(e2.y, 0.f), nf1[i].y, s5);
        s6 = fmaf(fmaxf(e3.x, 0.f), nf1[i].z, s6);
        s7 = fmaf(fmaxf(e3.y, 0.f), nf1[i].w, s7);
    }
    float* hp = &g_hsum[(size_t)cur * IN_F + c0];
    red_add_v4(hp,     s0, s1, s2, s3);
    red_add_v4(hp + 4, s4, s5, s6, s7);
}

// divide by degree + build concat h = [nfeat | mean]
__global__ void k_finalize0(const float* __restrict__ nfeat) {
    int i = blockIdx.x * blockDim.x + threadIdx.x;
    if (i >= N_NODES * IN_F) return;
    int n = i / IN_F, c = i % IN_F;
    int deg = g_rowptr[n + 1] - g_rowptr[n];
    float inv = 1.f / fmaxf((float)deg, 1.f);
    g_h[n * H0_F + c]        = nfeat[i];
    g_h[n * H0_F + IN_F + c] = g_hsum[i] * inv;
}

// ---------------- mean96: warp per node, unroll-2 dual accumulators ----------------
__global__ void __launch_bounds__(256) k_mean96() {
    int gw = (blockIdx.x * blockDim.x + threadIdx.x) >> 5;
    int l  = threadIdx.x & 31;
    if (gw >= N_NODES) return;
    int beg = g_rowptr[gw], end = g_rowptr[gw + 1];
    float a0 = 0.f, a1 = 0.f, a2 = 0.f, b0 = 0.f, b1 = 0.f, b2 = 0.f;
    int j = beg;
    for (; j + 2 <= end; j += 2) {
        const float* ra = &g_h[(size_t)g_csr[j].x     * H0_F];
        const float* rb = &g_h[(size_t)g_csr[j + 1].x * H0_F];
        a0 += __ldg(ra + l);      a1 += __ldg(ra + 32 + l); a2 += __ldg(ra + 64 + l);
        b0 += __ldg(rb + l);      b1 += __ldg(rb + 32 + l); b2 += __ldg(rb + 64 + l);
    }
    if (j < end) {
        const float* ra = &g_h[(size_t)g_csr[j].x * H0_F];
        a0 += __ldg(ra + l); a1 += __ldg(ra + 32 + l); a2 += __ldg(ra + 64 + l);
    }
    float inv = 1.f / fmaxf((float)(end - beg), 1.f);
    float* o = &g_hn1[(size_t)gw * H0_F];
    o[l] = (a0 + b0) * inv; o[32 + l] = (a1 + b1) * inv; o[64 + l] = (a2 + b2) * inv;
}

// ---------------- GEMM1: g_h1 = relu(g_h@W1s + g_hn1@W1n + b1) ----------------
__global__ void __launch_bounds__(256) k_gemm1(
    const float* __restrict__ Wa, const float* __restrict__ Wb,
    const float* __restrict__ bias)
{
    constexpr int BM = 128, BK = 32, NOUT = HID_F, APAD = BM + 4;
    __shared__ float AsT[BK][APAD];
    __shared__ float Bs[BK][NOUT];

    int t  = threadIdx.x;
    int tx = t & 15, ty = t >> 4;
    int brow = blockIdx.x * BM;
    int r0 = ty * 8, c0 = tx * 8;

    unsigned long long acc2[8][4];
    #pragma unroll
    for (int m = 0; m < 8; m++)
        #pragma unroll
        for (int j = 0; j < 4; j++) acc2[m][j] = pack2(0.f, 0.f);

    #pragma unroll
    for (int phase = 0; phase < 2; phase++) {
        const float* A = phase ? g_hn1 : g_h;
        const float* W = phase ? Wb : Wa;
        for (int kt = 0; kt < H0_F; kt += BK) {
            #pragma unroll
            for (int i = 0; i < 4; i++) {
                int idx = t + i * 256;
                int r = idx >> 3, c4 = idx & 7;
                int grow = brow + r;
                float4 v = make_float4(0.f, 0.f, 0.f, 0.f);
                if (grow < N_NODES)
                    v = *(const float4*)&A[(size_t)grow * H0_F + kt + c4 * 4];
                int pos = r ^ (8 * (c4 & 3));
                AsT[4 * c4 + 0][pos] = v.x;
                AsT[4 * c4 + 1][pos] = v.y;
                AsT[4 * c4 + 2][pos] = v.z;
                AsT[4 * c4 + 3][pos] = v.w;
            }
            #pragma unroll
            for (int i = 0; i < 4; i++) {
                int idx = t + i * 256;
                int r = idx >> 5, c4 = idx & 31;
                *(float4*)&Bs[r][c4 * 4] = *(const float4*)&W[(size_t)(kt + r) * NOUT + c4 * 4];
            }
            __syncthreads();
            #pragma unroll 8
            for (int k = 0; k < BK; k++) {
                int rs = r0 ^ (8 * ((k >> 2) & 3));
                float4 alo = *(const float4*)&AsT[k][rs];
                float4 ahi = *(const float4*)&AsT[k][rs + 4];
                ulonglong2 bA = *(const ulonglong2*)&Bs[k][c0];
                ulonglong2 bB = *(const ulonglong2*)&Bs[k][c0 + 4];
                unsigned long long bb0 = bA.x, bb1 = bA.y, bb2 = bB.x, bb3 = bB.y;
                float a[8] = {alo.x, alo.y, alo.z, alo.w, ahi.x, ahi.y, ahi.z, ahi.w};
                #pragma unroll
                for (int m = 0; m < 8; m++) {
                    unsigned long long am = pack2(a[m], a[m]);
                    acc2[m][0] = fma2(am, bb0, acc2[m][0]);
                    acc2[m][1] = fma2(am, bb1, acc2[m][1]);
                    acc2[m][2] = fma2(am, bb2, acc2[m][2]);
                    acc2[m][3] = fma2(am, bb3, acc2[m][3]);
                }
            }
            __syncthreads();
        }
    }
    #pragma unroll
    for (int m = 0; m < 8; m++) {
        int grow = brow + r0 + m;
        if (grow < N_NODES) {
            #pragma unroll
            for (int j = 0; j < 4; j++) {
                float2 c2 = unpack2(acc2[m][j]);
                float v0 = fmaxf(c2.x + bias[c0 + 2 * j],     0.f);
                float v1 = fmaxf(c2.y + bias[c0 + 2 * j + 1], 0.f);
                *(float2*)&g_h1[(size_t)grow * HID_F + c0 + 2 * j] = make_float2(v0, v1);
            }
        }
    }
}

// ---------------- GEMM2: g_s2z = [h1@W2s + b2 | h1@W2n] ----------------
__global__ void __launch_bounds__(256) k_gemm2(
    const float* __restrict__ Wa, const float* __restrict__ Wb,
    const float* __restrict__ bias)
{
    constexpr int BM = 128, BK = 32, NOUT = 128, APAD = BM + 4;
    __shared__ float AsT[BK][APAD];
    __shared__ float Bs[BK][NOUT];

    int t  = threadIdx.x;
    int tx = t & 15, ty = t >> 4;
    int brow = blockIdx.x * BM;
    int r0 = ty * 8, c0 = tx * 8;

    unsigned long long acc2[8][4];
    #pragma unroll
    for (int m = 0; m < 8; m++)
        #pragma unroll
        for (int j = 0; j < 4; j++) acc2[m][j] = pack2(0.f, 0.f);

    for (int kt = 0; kt < HID_F; kt += BK) {
        #pragma unroll
        for (int i = 0; i < 4; i++) {
            int idx = t + i * 256;
            int r = idx >> 3, c4 = idx & 7;
            int grow = brow + r;
            float4 v = make_float4(0.f, 0.f, 0.f, 0.f);
            if (grow < N_NODES)
                v = *(const float4*)&g_h1[(size_t)grow * HID_F + kt + c4 * 4];
            int pos = r ^ (8 * (c4 & 3));
            AsT[4 * c4 + 0][pos] = v.x;
            AsT[4 * c4 + 1][pos] = v.y;
            AsT[4 * c4 + 2][pos] = v.z;
            AsT[4 * c4 + 3][pos] = v.w;
        }
        #pragma unroll
        for (int i = 0; i < 4; i++) {
            int idx = t + i * 256;
            int r = idx >> 5, c4 = idx & 31;
            float4 v;
            if (c4 < 16) v = *(const float4*)&Wa[(size_t)(kt + r) * OUT_F + c4 * 4];
            else         v = *(const float4*)&Wb[(size_t)(kt + r) * OUT_F + (c4 - 16) * 4];
            *(float4*)&Bs[r][c4 * 4] = v;
        }
        __syncthreads();
        #pragma unroll 8
        for (int k = 0; k < BK; k++) {
            int rs = r0 ^ (8 * ((k >> 2) & 3));
            float4 alo = *(const float4*)&AsT[k][rs];
            float4 ahi = *(const float4*)&AsT[k][rs + 4];
            ulonglong2 bA = *(const ulonglong2*)&Bs[k][c0];
            ulonglong2 bB = *(const ulonglong2*)&Bs[k][c0 + 4];
            unsigned long long bb0 = bA.x, bb1 = bA.y, bb2 = bB.x, bb3 = bB.y;
            float a[8] = {alo.x, alo.y, alo.z, alo.w, ahi.x, ahi.y, ahi.z, ahi.w};
            #pragma unroll
            for (int m = 0; m < 8; m++) {
                unsigned long long am = pack2(a[m], a[m]);
                acc2[m][0] = fma2(am, bb0, acc2[m][0]);
                acc2[m][1] = fma2(am, bb1, acc2[m][1]);
                acc2[m][2] = fma2(am, bb2, acc2[m][2]);
                acc2[m][3] = fma2(am, bb3, acc2[m][3]);
            }
        }
        __syncthreads();
    }
    #pragma unroll
    for (int m = 0; m < 8; m++) {
        int grow = brow + r0 + m;
        if (grow < N_NODES) {
            #pragma unroll
            for (int j = 0; j < 4; j++) {
                int col = c0 + 2 * j;
                float2 c2 = unpack2(acc2[m][j]);
                float v0 = c2.x + (col     < OUT_F ? bias[col]     : 0.f);
                float v1 = c2.y + (col + 1 < OUT_F ? bias[col + 1] : 0.f);
                *(float2*)&g_s2z[(size_t)grow * 128 + col] = make_float2(v0, v1);
            }
        }
    }
}

// ---------------- final: out = S2 + seg_mean(Z[src]) ----------------
__global__ void __launch_bounds__(256) k_final(float* __restrict__ out) {
    int gw = (blockIdx.x * blockDim.x + threadIdx.x) >> 5;
    int l  = threadIdx.x & 31;
    if (gw >= N_NODES) return;
    int beg = g_rowptr[gw], end = g_rowptr[gw + 1];
    float a0 = 0.f, a1 = 0.f, b0 = 0.f, b1 = 0.f;
    int j = beg;
    for (; j + 2 <= end; j += 2) {
        const float* ra = &g_s2z[(size_t)g_csr[j].x     * 128 + OUT_F];
        const float* rb = &g_s2z[(size_t)g_csr[j + 1].x * 128 + OUT_F];
        a0 += __ldg(ra + l); a1 += __ldg(ra + 32 + l);
        b0 += __ldg(rb + l); b1 += __ldg(rb + 32 + l);
    }
    if (j < end) {
        const float* ra = &g_s2z[(size_t)g_csr[j].x * 128 + OUT_F];
        a0 += __ldg(ra + l); a1 += __ldg(ra + 32 + l);
    }
    float inv = 1.f / fmaxf((float)(end - beg), 1.f);
    const float* s2 = &g_s2z[(size_t)gw * 128];
    out[(size_t)gw * OUT_F + l]      = s2[l]      + (a0 + b0) * inv;
    out[(size_t)gw * OUT_F + 32 + l] = s2[32 + l] + (a1 + b1) * inv;
}

// ---------------- launch ----------------
extern "C" void kernel_launch(void* const* d_in, const int* in_sizes, int n_in,
                              void* d_out, int out_size)
{
    const float* nfeat = (const float*)d_in[0];
    const float* efeat = (const float*)d_in[1];
    const int*   src   = (const int*)d_in[2];
    const int*   dst   = (const int*)d_in[3];
    const float* We    = (const float*)d_in[4];
    const float* be    = (const float*)d_in[5];
    const float* W1s   = (const float*)d_in[6];
    const float* W1n   = (const float*)d_in[7];
    const float* b1    = (const float*)d_in[8];
    const float* W2s   = (const float*)d_in[9];
    const float* W2n   = (const float*)d_in[10];
    const float* b2    = (const float*)d_in[11];
    float* out = (float*)d_out;

    const int WARP_GRID = (N_NODES * 32 + 255) / 256;

    void* p = nullptr;
    cudaGetSymbolAddress(&p, g_deg);
    cudaMemsetAsync(p, 0, N_NODES * sizeof(int));
    cudaGetSymbolAddress(&p, g_hsum);
    cudaMemsetAsync(p, 0, (size_t)N_NODES * IN_F * sizeof(float));

    k_deg<<<(N_EDGES + 255) / 256, 256>>>(dst);
    k_scan<<<1, 1024>>>();
    k_fill<<<(N_EDGES + 255) / 256, 256>>>(src, dst);
    k_layer0_gemm<<<N_EDGES / L0_TILE, L0_THREADS>>>(nfeat, efeat, We, be);
    k_finalize0<<<(N_NODES * IN_F + 255) / 256, 256>>>(nfeat);
    k_mean96<<<WARP_GRID, 256>>>();
    k_gemm1<<<(N_NODES + 127) / 128, 256>>>(W1s, W1n, b1);
    k_gemm2<<<(N_NODES + 127) / 128, 256>>>(W2s, W2n, b2);
    k_final<<<WARP_GRID, 256>>>(out);
}

// round 11
// speedup vs baseline: 2.0184x; 1.1220x over previous
#include <cuda_runtime.h>

#define N_NODES 100000
#define N_EDGES 1600000
#define IN_F    48
#define EDGE_F  32
#define HID_F   128
#define OUT_F   64
#define H0_F    96   // 2*IN_F
#define SCAN_NB 98   // ceil(N_NODES/1024)

// ---------------- scratch (static device allocations only) ----------------
__device__ int   g_deg[N_NODES];
__device__ int   g_rowptr[N_NODES + 1];
__device__ int   g_cursor[N_NODES];
__device__ int   g_bsum[128];
__device__ int   g_boff[128];
__device__ int4  g_csr[N_EDGES];           // (src, eid, dst, pad) packed
__device__ float g_hsum[N_NODES * IN_F];   // layer0 aggregated sums (pre-mean)
__device__ float g_h  [N_NODES * H0_F];    // concat(nfeat, h_neigh0)
__device__ float g_hn1[N_NODES * H0_F];    // seg_mean(h[src])
__device__ float g_h1 [N_NODES * HID_F];   // layer1 output
__device__ float g_s2z[N_NODES * 128];     // [h1@W2s+b2 | h1@W2n]

// ---------------- packed f32x2 helpers ----------------
__device__ __forceinline__ unsigned long long pack2(float lo, float hi) {
    unsigned long long u;
    asm("mov.b64 %0, {%1, %2};" : "=l"(u) : "f"(lo), "f"(hi));
    return u;
}
__device__ __forceinline__ float2 unpack2(unsigned long long u) {
    float lo, hi;
    asm("mov.b64 {%0, %1}, %2;" : "=f"(lo), "=f"(hi) : "l"(u));
    return make_float2(lo, hi);
}
__device__ __forceinline__ unsigned long long fma2(unsigned long long a,
                                                   unsigned long long b,
                                                   unsigned long long c) {
    unsigned long long d;
    asm("fma.rn.f32x2 %0, %1, %2, %3;" : "=l"(d) : "l"(a), "l"(b), "l"(c));
    return d;
}
// vector reduction: 4 floats in one red op (sm_90+)
__device__ __forceinline__ void red_add_v4(float* p, float a, float b, float c, float d) {
    asm volatile("red.global.add.v4.f32 [%0], {%1, %2, %3, %4};"
                 :: "l"(p), "f"(a), "f"(b), "f"(c), "f"(d) : "memory");
}

// ---------------- CSR build ----------------
__global__ void k_deg(const int* __restrict__ dst) {
    int i = blockIdx.x * blockDim.x + threadIdx.x;
    if (i < N_EDGES) atomicAdd(&g_deg[dst[i]], 1);
}

// parallel scan, phase 1: per-block exclusive scan + block sums
__global__ void k_scan_blocks() {
    __shared__ int wsum[32];
    int t = threadIdx.x, lane = t & 31, w = t >> 5;
    int i = blockIdx.x * 1024 + t;
    int v = (i < N_NODES) ? g_deg[i] : 0;
    int x = v;
    #pragma unroll
    for (int o = 1; o < 32; o <<= 1) {
        int y = __shfl_up_sync(0xffffffffu, x, o);
        if (lane >= o) x += y;
    }
    if (lane == 31) wsum[w] = x;
    __syncthreads();
    if (w == 0) {
        int s = wsum[lane];
        #pragma unroll
        for (int o = 1; o < 32; o <<= 1) {
            int y = __shfl_up_sync(0xffffffffu, s, o);
            if (lane >= o) s += y;
        }
        wsum[lane] = s;
    }
    __syncthreads();
    int excl = (w ? wsum[w - 1] : 0) + (x - v);
    if (i < N_NODES) g_rowptr[i] = excl;
    if (t == 0) g_bsum[blockIdx.x] = wsum[31];
}

// phase 2: one warp scans block sums
__global__ void k_scan_top() {
    int l = threadIdx.x;  // 32 threads
    int running = 0;
    for (int base = 0; base < SCAN_NB; base += 32) {
        int v = (base + l < SCAN_NB) ? g_bsum[base + l] : 0;
        int x = v;
        #pragma unroll
        for (int o = 1; o < 32; o <<= 1) {
            int y = __shfl_up_sync(0xffffffffu, x, o);
            if (l >= o) x += y;
        }
        if (base + l < SCAN_NB) g_boff[base + l] = running + x - v;
        running += __shfl_sync(0xffffffffu, x, 31);
    }
    if (l == 0) g_rowptr[N_NODES] = running;
}

// phase 3: add block offsets, init cursor
__global__ void k_scan_add() {
    int i = blockIdx.x * blockDim.x + threadIdx.x;
    if (i < N_NODES) {
        int rp = g_rowptr[i] + g_boff[i >> 10];
        g_rowptr[i] = rp;
        g_cursor[i] = rp;
    }
}

__global__ void k_fill(const int* __restrict__ src, const int* __restrict__ dst) {
    int i = blockIdx.x * blockDim.x + threadIdx.x;
    if (i < N_EDGES) {
        int d = dst[i];
        int p = atomicAdd(&g_cursor[d], 1);
        g_csr[p] = make_int4(src[i], i, d, 0);
    }
}

// ---------------- layer0: register-tiled edge GEMM + segment reduce ----------------
// Block = 128 CSR slots, 192 threads: 32 row-tiles(4 rows) x 6 col-tiles(8 cols).
// 4 blocks/SM -> 4 independent barrier domains for gather-latency overlap.
#define L0_TILE    128
#define L0_THREADS 192

__global__ void __launch_bounds__(L0_THREADS, 4) k_layer0_gemm(
    const float* __restrict__ nfeat, const float* __restrict__ efeat,
    const float* __restrict__ We, const float* __restrict__ be)
{
    __shared__ float AsT[EDGE_F][L0_TILE];   // k-major efeat tile, XOR swizzled
    __shared__ float Bs[EDGE_F][IN_F];       // 32x48 weights
    __shared__ float bes[IN_F];
    __shared__ int   srcs_s[L0_TILE];
    __shared__ int   dsts_s[L0_TILE];
    __shared__ int   eids_s[L0_TILE];

    const int t  = threadIdx.x;
    const int j0 = blockIdx.x * L0_TILE;

    if (t < L0_TILE) {
        int4 v = g_csr[j0 + t];
        srcs_s[t] = v.x;
        eids_s[t] = v.y;
        dsts_s[t] = v.z;
    }
    // weights: 32x48 floats = 384 float4s
    for (int idx = t; idx < 384; idx += L0_THREADS) {
        int r = idx / 12, c4 = idx % 12;
        *(float4*)&Bs[r][c4 * 4] = *(const float4*)&We[r * IN_F + c4 * 4];
    }
    if (t < IN_F) bes[t] = be[t];
    __syncthreads();

    // gather efeat rows -> AsT (k-major, swizzled: pos = row ^ (8*(c4&3)))
    for (int idx = t; idx < L0_TILE * 8; idx += L0_THREADS) {
        int row = idx >> 3, c4 = idx & 7;
        float4 v = *(const float4*)&efeat[(size_t)eids_s[row] * EDGE_F + c4 * 4];
        int pos = row ^ (8 * (c4 & 3));
        AsT[4 * c4 + 0][pos] = v.x;
        AsT[4 * c4 + 1][pos] = v.y;
        AsT[4 * c4 + 2][pos] = v.z;
        AsT[4 * c4 + 3][pos] = v.w;
    }
    __syncthreads();

    const int rt = t & 31;          // row tile 0..31 (4 rows each)
    const int ct = t >> 5;          // col tile 0..5 (8 cols each)
    const int r0 = rt * 4, c0 = ct * 8;

    unsigned long long acc2[4][4];
    {
        unsigned long long b0 = pack2(bes[c0 + 0], bes[c0 + 1]);
        unsigned long long b1 = pack2(bes[c0 + 2], bes[c0 + 3]);
        unsigned long long b2v = pack2(bes[c0 + 4], bes[c0 + 5]);
        unsigned long long b3 = pack2(bes[c0 + 6], bes[c0 + 7]);
        #pragma unroll
        for (int m = 0; m < 4; m++) {
            acc2[m][0] = b0; acc2[m][1] = b1; acc2[m][2] = b2v; acc2[m][3] = b3;
        }
    }

    #pragma unroll 8
    for (int k = 0; k < EDGE_F; k++) {
        int rs = r0 ^ (8 * ((k >> 2) & 3));
        float4 av = *(const float4*)&AsT[k][rs];
        ulonglong2 bA = *(const ulonglong2*)&Bs[k][c0];
        ulonglong2 bB = *(const ulonglong2*)&Bs[k][c0 + 4];
        unsigned long long bb0 = bA.x, bb1 = bA.y, bb2 = bB.x, bb3 = bB.y;
        float a[4] = {av.x, av.y, av.z, av.w};
        #pragma unroll
        for (int m = 0; m < 4; m++) {
            unsigned long long am = pack2(a[m], a[m]);
            acc2[m][0] = fma2(am, bb0, acc2[m][0]);
            acc2[m][1] = fma2(am, bb1, acc2[m][1]);
            acc2[m][2] = fma2(am, bb2, acc2[m][2]);
            acc2[m][3] = fma2(am, bb3, acc2[m][3]);
        }
    }

    // epilogue: batch nfeat gathers (8 independent LDG.128), segment scan, v4 red flush
    float4 nf0[4], nf1[4];
    #pragma unroll
    for (int i = 0; i < 4; i++) {
        const float* nf = &nfeat[(size_t)srcs_s[r0 + i] * IN_F + c0];
        nf0[i] = *(const float4*)nf;
        nf1[i] = *(const float4*)(nf + 4);
    }

    float s0 = 0.f, s1 = 0.f, s2 = 0.f, s3 = 0.f, s4 = 0.f, s5 = 0.f, s6 = 0.f, s7 = 0.f;
    int cur = dsts_s[r0];
    #pragma unroll
    for (int i = 0; i < 4; i++) {
        int d = dsts_s[r0 + i];
        if (d != cur) {
            float* hp = &g_hsum[(size_t)cur * IN_F + c0];
            red_add_v4(hp,     s0, s1, s2, s3);
            red_add_v4(hp + 4, s4, s5, s6, s7);
            s0 = s1 = s2 = s3 = s4 = s5 = s6 = s7 = 0.f;
            cur = d;
        }
        float2 e0 = unpack2(acc2[i][0]);
        float2 e1 = unpack2(acc2[i][1]);
        float2 e2 = unpack2(acc2[i][2]);
        float2 e3 = unpack2(acc2[i][3]);
        s0 = fmaf(fmaxf(e0.x, 0.f), nf0[i].x, s0);
        s1 = fmaf(fmaxf(e0.y, 0.f), nf0[i].y, s1);
        s2 = fmaf(fmaxf(e1.x, 0.f), nf0[i].z, s2);
        s3 = fmaf(fmaxf(e1.y, 0.f), nf0[i].w, s3);
        s4 = fmaf(fmaxf(e2.x, 0.f), nf1[i].x, s4);
        s5 = fmaf(fmaxf(e2.y, 0.f), nf1[i].y, s5);
        s6 = fmaf(fmaxf(e3.x, 0.f), nf1[i].z, s6);
        s7 = fmaf(fmaxf(e3.y, 0.f), nf1[i].w, s7);
    }
    float* hp = &g_hsum[(size_t)cur * IN_F + c0];
    red_add_v4(hp,     s0, s1, s2, s3);
    red_add_v4(hp + 4, s4, s5, s6, s7);
}

// divide by degree + build concat h = [nfeat | mean]
__global__ void k_finalize0(const float* __restrict__ nfeat) {
    int i = blockIdx.x * blockDim.x + threadIdx.x;
    if (i >= N_NODES * IN_F) return;
    int n = i / IN_F, c = i % IN_F;
    int deg = g_rowptr[n + 1] - g_rowptr[n];
    float inv = 1.f / fmaxf((float)deg, 1.f);
    g_h[n * H0_F + c]        = nfeat[i];
    g_h[n * H0_F + IN_F + c] = g_hsum[i] * inv;
}

// ---------------- mean96: warp per node, float4 lanes (24 active) ----------------
__global__ void __launch_bounds__(256) k_mean96() {
    int gw = (blockIdx.x * blockDim.x + threadIdx.x) >> 5;
    int l  = threadIdx.x & 31;
    if (gw >= N_NODES || l >= 24) return;
    int beg = g_rowptr[gw], end = g_rowptr[gw + 1];
    float4 A = make_float4(0.f, 0.f, 0.f, 0.f);
    float4 B = make_float4(0.f, 0.f, 0.f, 0.f);
    int j = beg;
    for (; j + 2 <= end; j += 2) {
        float4 va = ((const float4*)&g_h[(size_t)g_csr[j].x     * H0_F])[l];
        float4 vb = ((const float4*)&g_h[(size_t)g_csr[j + 1].x * H0_F])[l];
        A.x += va.x; A.y += va.y; A.z += va.z; A.w += va.w;
        B.x += vb.x; B.y += vb.y; B.z += vb.z; B.w += vb.w;
    }
    if (j < end) {
        float4 va = ((const float4*)&g_h[(size_t)g_csr[j].x * H0_F])[l];
        A.x += va.x; A.y += va.y; A.z += va.z; A.w += va.w;
    }
    float inv = 1.f / fmaxf((float)(end - beg), 1.f);
    float4 r;
    r.x = (A.x + B.x) * inv; r.y = (A.y + B.y) * inv;
    r.z = (A.z + B.z) * inv; r.w = (A.w + B.w) * inv;
    ((float4*)&g_hn1[(size_t)gw * H0_F])[l] = r;
}

// ---------------- GEMM1: g_h1 = relu(g_h@W1s + g_hn1@W1n + b1), BK=48 ----------------
__global__ void __launch_bounds__(256) k_gemm1(
    const float* __restrict__ Wa, const float* __restrict__ Wb,
    const float* __restrict__ bias)
{
    constexpr int BM = 128, BK = 48, NOUT = HID_F, APAD = BM + 4;
    __shared__ float AsT[BK][APAD];
    __shared__ float Bs[BK][NOUT];

    int t  = threadIdx.x;
    int tx = t & 15, ty = t >> 4;
    int brow = blockIdx.x * BM;
    int r0 = ty * 8, c0 = tx * 8;

    unsigned long long acc2[8][4];
    #pragma unroll
    for (int m = 0; m < 8; m++)
        #pragma unroll
        for (int j = 0; j < 4; j++) acc2[m][j] = pack2(0.f, 0.f);

    #pragma unroll
    for (int phase = 0; phase < 2; phase++) {
        const float* A = phase ? g_hn1 : g_h;
        const float* W = phase ? Wb : Wa;
        for (int kt = 0; kt < H0_F; kt += BK) {
            // A tile: 128 rows x 48 k = 1536 float4s
            #pragma unroll
            for (int i = 0; i < 6; i++) {
                int idx = t + i * 256;
                int r = idx / 12, c4 = idx % 12;
                int grow = brow + r;
                float4 v = make_float4(0.f, 0.f, 0.f, 0.f);
                if (grow < N_NODES)
                    v = *(const float4*)&A[(size_t)grow * H0_F + kt + c4 * 4];
                int pos = r ^ (8 * (c4 & 3));
                AsT[4 * c4 + 0][pos] = v.x;
                AsT[4 * c4 + 1][pos] = v.y;
                AsT[4 * c4 + 2][pos] = v.z;
                AsT[4 * c4 + 3][pos] = v.w;
            }
            // B tile: 48 x 128 = 1536 float4s
            #pragma unroll
            for (int i = 0; i < 6; i++) {
                int idx = t + i * 256;
                int r = idx >> 5, c4 = idx & 31;
                *(float4*)&Bs[r][c4 * 4] = *(const float4*)&W[(size_t)(kt + r) * NOUT + c4 * 4];
            }
            __syncthreads();
            #pragma unroll 8
            for (int k = 0; k < BK; k++) {
                int rs = r0 ^ (8 * ((k >> 2) & 3));
                float4 alo = *(const float4*)&AsT[k][rs];
                float4 ahi = *(const float4*)&AsT[k][rs + 4];
                ulonglong2 bA = *(const ulonglong2*)&Bs[k][c0];
                ulonglong2 bB = *(const ulonglong2*)&Bs[k][c0 + 4];
                unsigned long long bb0 = bA.x, bb1 = bA.y, bb2 = bB.x, bb3 = bB.y;
                float a[8] = {alo.x, alo.y, alo.z, alo.w, ahi.x, ahi.y, ahi.z, ahi.w};
                #pragma unroll
                for (int m = 0; m < 8; m++) {
                    unsigned long long am = pack2(a[m], a[m]);
                    acc2[m][0] = fma2(am, bb0, acc2[m][0]);
                    acc2[m][1] = fma2(am, bb1, acc2[m][1]);
                    acc2[m][2] = fma2(am, bb2, acc2[m][2]);
                    acc2[m][3] = fma2(am, bb3, acc2[m][3]);
                }
            }
            __syncthreads();
        }
    }
    #pragma unroll
    for (int m = 0; m < 8; m++) {
        int grow = brow + r0 + m;
        if (grow < N_NODES) {
            #pragma unroll
            for (int j = 0; j < 4; j++) {
                float2 c2 = unpack2(acc2[m][j]);
                float v0 = fmaxf(c2.x + bias[c0 + 2 * j],     0.f);
                float v1 = fmaxf(c2.y + bias[c0 + 2 * j + 1], 0.f);
                *(float2*)&g_h1[(size_t)grow * HID_F + c0 + 2 * j] = make_float2(v0, v1);
            }
        }
    }
}

// ---------------- GEMM2: g_s2z = [h1@W2s + b2 | h1@W2n] ----------------
__global__ void __launch_bounds__(256) k_gemm2(
    const float* __restrict__ Wa, const float* __restrict__ Wb,
    const float* __restrict__ bias)
{
    constexpr int BM = 128, BK = 32, NOUT = 128, APAD = BM + 4;
    __shared__ float AsT[BK][APAD];
    __shared__ float Bs[BK][NOUT];

    int t  = threadIdx.x;
    int tx = t & 15, ty = t >> 4;
    int brow = blockIdx.x * BM;
    int r0 = ty * 8, c0 = tx * 8;

    unsigned long long acc2[8][4];
    #pragma unroll
    for (int m = 0; m < 8; m++)
        #pragma unroll
        for (int j = 0; j < 4; j++) acc2[m][j] = pack2(0.f, 0.f);

    for (int kt = 0; kt < HID_F; kt += BK) {
        #pragma unroll
        for (int i = 0; i < 4; i++) {
            int idx = t + i * 256;
            int r = idx >> 3, c4 = idx & 7;
            int grow = brow + r;
            float4 v = make_float4(0.f, 0.f, 0.f, 0.f);
            if (grow < N_NODES)
                v = *(const float4*)&g_h1[(size_t)grow * HID_F + kt + c4 * 4];
            int pos = r ^ (8 * (c4 & 3));
            AsT[4 * c4 + 0][pos] = v.x;
            AsT[4 * c4 + 1][pos] = v.y;
            AsT[4 * c4 + 2][pos] = v.z;
            AsT[4 * c4 + 3][pos] = v.w;
        }
        #pragma unroll
        for (int i = 0; i < 4; i++) {
            int idx = t + i * 256;
            int r = idx >> 5, c4 = idx & 31;
            float4 v;
            if (c4 < 16) v = *(const float4*)&Wa[(size_t)(kt + r) * OUT_F + c4 * 4];
            else         v = *(const float4*)&Wb[(size_t)(kt + r) * OUT_F + (c4 - 16) * 4];
            *(float4*)&Bs[r][c4 * 4] = v;
        }
        __syncthreads();
        #pragma unroll 8
        for (int k = 0; k < BK; k++) {
            int rs = r0 ^ (8 * ((k >> 2) & 3));
            float4 alo = *(const float4*)&AsT[k][rs];
            float4 ahi = *(const float4*)&AsT[k][rs + 4];
            ulonglong2 bA = *(const ulonglong2*)&Bs[k][c0];
            ulonglong2 bB = *(const ulonglong2*)&Bs[k][c0 + 4];
            unsigned long long bb0 = bA.x, bb1 = bA.y, bb2 = bB.x, bb3 = bB.y;
            float a[8] = {alo.x, alo.y, alo.z, alo.w, ahi.x, ahi.y, ahi.z, ahi.w};
            #pragma unroll
            for (int m = 0; m < 8; m++) {
                unsigned long long am = pack2(a[m], a[m]);
                acc2[m][0] = fma2(am, bb0, acc2[m][0]);
                acc2[m][1] = fma2(am, bb1, acc2[m][1]);
                acc2[m][2] = fma2(am, bb2, acc2[m][2]);
                acc2[m][3] = fma2(am, bb3, acc2[m][3]);
            }
        }
        __syncthreads();
    }
    #pragma unroll
    for (int m = 0; m < 8; m++) {
        int grow = brow + r0 + m;
        if (grow < N_NODES) {
            #pragma unroll
            for (int j = 0; j < 4; j++) {
                int col = c0 + 2 * j;
                float2 c2 = unpack2(acc2[m][j]);
                float v0 = c2.x + (col     < OUT_F ? bias[col]     : 0.f);
                float v1 = c2.y + (col + 1 < OUT_F ? bias[col + 1] : 0.f);
                *(float2*)&g_s2z[(size_t)grow * 128 + col] = make_float2(v0, v1);
            }
        }
    }
}

// ---------------- final: out = S2 + seg_mean(Z[src]); half-warp per node ----------------
__global__ void __launch_bounds__(256) k_final(float* __restrict__ out) {
    int gt  = blockIdx.x * blockDim.x + threadIdx.x;
    int ghw = gt >> 4;            // half-warp id = node
    int hl  = gt & 15;            // 16 lanes x float4 = 64 cols
    if (ghw >= N_NODES) return;
    int beg = g_rowptr[ghw], end = g_rowptr[ghw + 1];
    float4 A = make_float4(0.f, 0.f, 0.f, 0.f);
    float4 B = make_float4(0.f, 0.f, 0.f, 0.f);
    int j = beg;
    for (; j + 2 <= end; j += 2) {
        float4 va = ((const float4*)&g_s2z[(size_t)g_csr[j].x     * 128 + OUT_F])[hl];
        float4 vb = ((const float4*)&g_s2z[(size_t)g_csr[j + 1].x * 128 + OUT_F])[hl];
        A.x += va.x; A.y += va.y; A.z += va.z; A.w += va.w;
        B.x += vb.x; B.y += vb.y; B.z += vb.z; B.w += vb.w;
    }
    if (j < end) {
        float4 va = ((const float4*)&g_s2z[(size_t)g_csr[j].x * 128 + OUT_F])[hl];
        A.x += va.x; A.y += va.y; A.z += va.z; A.w += va.w;
    }
    float inv = 1.f / fmaxf((float)(end - beg), 1.f);
    float4 s2 = ((const float4*)&g_s2z[(size_t)ghw * 128])[hl];
    float4 r;
    r.x = s2.x + (A.x + B.x) * inv;
    r.y = s2.y + (A.y + B.y) * inv;
    r.z = s2.z + (A.z + B.z) * inv;
    r.w = s2.w + (A.w + B.w) * inv;
    ((float4*)&out[(size_t)ghw * OUT_F])[hl] = r;
}

// ---------------- launch ----------------
extern "C" void kernel_launch(void* const* d_in, const int* in_sizes, int n_in,
                              void* d_out, int out_size)
{
    const float* nfeat = (const float*)d_in[0];
    const float* efeat = (const float*)d_in[1];
    const int*   src   = (const int*)d_in[2];
    const int*   dst   = (const int*)d_in[3];
    const float* We    = (const float*)d_in[4];
    const float* be    = (const float*)d_in[5];
    const float* W1s   = (const float*)d_in[6];
    const float* W1n   = (const float*)d_in[7];
    const float* b1    = (const float*)d_in[8];
    const float* W2s   = (const float*)d_in[9];
    const float* W2n   = (const float*)d_in[10];
    const float* b2    = (const float*)d_in[11];
    float* out = (float*)d_out;

    const int WARP_GRID = (N_NODES * 32 + 255) / 256;   // warp-per-node kernels
    const int HW_GRID   = (N_NODES * 16 + 255) / 256;   // half-warp-per-node

    void* p = nullptr;
    cudaGetSymbolAddress(&p, g_deg);
    cudaMemsetAsync(p, 0, N_NODES * sizeof(int));
    cudaGetSymbolAddress(&p, g_hsum);
    cudaMemsetAsync(p, 0, (size_t)N_NODES * IN_F * sizeof(float));

    k_deg<<<(N_EDGES + 255) / 256, 256>>>(dst);
    k_scan_blocks<<<SCAN_NB, 1024>>>();
    k_scan_top<<<1, 32>>>();
    k_scan_add<<<SCAN_NB, 1024>>>();
    k_fill<<<(N_EDGES + 255) / 256, 256>>>(src, dst);
    k_layer0_gemm<<<N_EDGES / L0_TILE, L0_THREADS>>>(nfeat, efeat, We, be);
    k_finalize0<<<(N_NODES * IN_F + 255) / 256, 256>>>(nfeat);
    k_mean96<<<WARP_GRID, 256>>>();
    k_gemm1<<<(N_NODES + 127) / 128, 256>>>(W1s, W1n, b1);
    k_gemm2<<<(N_NODES + 127) / 128, 256>>>(W2s, W2n, b2);
    k_final<<<HW_GRID, 256>>>(out);
}

// round 12
// speedup vs baseline: 2.0367x; 1.0090x over previous
#include <cuda_runtime.h>

#define N_NODES 100000
#define N_EDGES 1600000
#define IN_F    48
#define EDGE_F  32
#define HID_F   128
#define OUT_F   64
#define H0_F    96   // 2*IN_F
#define SCAN_NB 98   // ceil(N_NODES/1024)

// ---------------- scratch (static device allocations only) ----------------
__device__ int   g_deg[N_NODES];
__device__ int   g_rowptr[N_NODES + 1];
__device__ int   g_cursor[N_NODES];
__device__ int   g_bsum[128];
__device__ int   g_boff[128];
__device__ int4  g_csr[N_EDGES];           // (src, eid, dst, pad) packed
__device__ float g_hsum[N_NODES * IN_F];   // layer0 aggregated sums (pre-mean)
__device__ float g_h  [N_NODES * H0_F];    // concat(nfeat, h_neigh0)
__device__ float g_hn1[N_NODES * H0_F];    // seg_mean(h[src])
__device__ float g_h1 [N_NODES * HID_F];   // layer1 output
__device__ float g_s2z[N_NODES * 128];     // [h1@W2s+b2 | h1@W2n]

// ---------------- packed f32x2 helpers ----------------
__device__ __forceinline__ unsigned long long pack2(float lo, float hi) {
    unsigned long long u;
    asm("mov.b64 %0, {%1, %2};" : "=l"(u) : "f"(lo), "f"(hi));
    return u;
}
__device__ __forceinline__ float2 unpack2(unsigned long long u) {
    float lo, hi;
    asm("mov.b64 {%0, %1}, %2;" : "=f"(lo), "=f"(hi) : "l"(u));
    return make_float2(lo, hi);
}
__device__ __forceinline__ unsigned long long fma2(unsigned long long a,
                                                   unsigned long long b,
                                                   unsigned long long c) {
    unsigned long long d;
    asm("fma.rn.f32x2 %0, %1, %2, %3;" : "=l"(d) : "l"(a), "l"(b), "l"(c));
    return d;
}
// vector reduction: 4 floats in one red op (sm_90+)
__device__ __forceinline__ void red_add_v4(float* p, float a, float b, float c, float d) {
    asm volatile("red.global.add.v4.f32 [%0], {%1, %2, %3, %4};"
                 :: "l"(p), "f"(a), "f"(b), "f"(c), "f"(d) : "memory");
}

// ---------------- CSR build ----------------
__global__ void k_deg(const int* __restrict__ dst) {
    int i = blockIdx.x * blockDim.x + threadIdx.x;
    if (i < N_EDGES) atomicAdd(&g_deg[dst[i]], 1);
}

// parallel scan, phase 1: per-block exclusive scan + block sums
__global__ void k_scan_blocks() {
    __shared__ int wsum[32];
    int t = threadIdx.x, lane = t & 31, w = t >> 5;
    int i = blockIdx.x * 1024 + t;
    int v = (i < N_NODES) ? g_deg[i] : 0;
    int x = v;
    #pragma unroll
    for (int o = 1; o < 32; o <<= 1) {
        int y = __shfl_up_sync(0xffffffffu, x, o);
        if (lane >= o) x += y;
    }
    if (lane == 31) wsum[w] = x;
    __syncthreads();
    if (w == 0) {
        int s = wsum[lane];
        #pragma unroll
        for (int o = 1; o < 32; o <<= 1) {
            int y = __shfl_up_sync(0xffffffffu, s, o);
            if (lane >= o) s += y;
        }
        wsum[lane] = s;
    }
    __syncthreads();
    int excl = (w ? wsum[w - 1] : 0) + (x - v);
    if (i < N_NODES) g_rowptr[i] = excl;
    if (t == 0) g_bsum[blockIdx.x] = wsum[31];
}

// phase 2: one warp scans block sums
__global__ void k_scan_top() {
    int l = threadIdx.x;  // 32 threads
    int running = 0;
    for (int base = 0; base < SCAN_NB; base += 32) {
        int v = (base + l < SCAN_NB) ? g_bsum[base + l] : 0;
        int x = v;
        #pragma unroll
        for (int o = 1; o < 32; o <<= 1) {
            int y = __shfl_up_sync(0xffffffffu, x, o);
            if (l >= o) x += y;
        }
        if (base + l < SCAN_NB) g_boff[base + l] = running + x - v;
        running += __shfl_sync(0xffffffffu, x, 31);
    }
    if (l == 0) g_rowptr[N_NODES] = running;
}

// phase 3: add block offsets, init cursor
__global__ void k_scan_add() {
    int i = blockIdx.x * blockDim.x + threadIdx.x;
    if (i < N_NODES) {
        int rp = g_rowptr[i] + g_boff[i >> 10];
        g_rowptr[i] = rp;
        g_cursor[i] = rp;
    }
}

__global__ void k_fill(const int* __restrict__ src, const int* __restrict__ dst) {
    int i = blockIdx.x * blockDim.x + threadIdx.x;
    if (i < N_EDGES) {
        int d = dst[i];
        int p = atomicAdd(&g_cursor[d], 1);
        g_csr[p] = make_int4(src[i], i, d, 0);
    }
}

// ---------------- layer0: pipelined register-tiled edge GEMM + segment reduce ----
// Block = 2 tiles of 128 CSR slots, 384 threads: 32 row-tiles(4) x 12 col-tiles(4).
// Double-buffered A tile with register prefetch: tile1's gather LDGs are in
// flight while tile0 computes.
#define L0_TILE    128
#define L0_THREADS 384

__global__ void __launch_bounds__(L0_THREADS, 2) k_layer0_gemm(
    const float* __restrict__ nfeat, const float* __restrict__ efeat,
    const float* __restrict__ We, const float* __restrict__ be)
{
    __shared__ float AsT[2][EDGE_F][L0_TILE]; // k-major efeat tiles, XOR swizzled
    __shared__ float Bs[EDGE_F][IN_F];        // 32x48 weights
    __shared__ float bes[IN_F];
    __shared__ int   srcs_s[2 * L0_TILE];
    __shared__ int   dsts_s[2 * L0_TILE];
    __shared__ int   eids_s[2 * L0_TILE];

    const int t  = threadIdx.x;
    const int j0 = blockIdx.x * 2 * L0_TILE;

    if (t < 2 * L0_TILE) {
        int4 v = g_csr[j0 + t];
        srcs_s[t] = v.x;
        eids_s[t] = v.y;
        dsts_s[t] = v.z;
    }
    if (t < 384) {  // weights: 32x48 floats = 384 float4s
        int r = t / 12, c4 = t % 12;
        *(float4*)&Bs[r][c4 * 4] = *(const float4*)&We[r * IN_F + c4 * 4];
    }
    if (t < IN_F) bes[t] = be[t];
    __syncthreads();

    // gather tile0 (3 iterations cover 1024 chunks with 384 threads)
    float4 pre[3];
    #pragma unroll
    for (int i = 0; i < 3; i++) {
        int idx = t + i * L0_THREADS;
        if (idx < L0_TILE * 8) {
            int row = idx >> 3, c4 = idx & 7;
            pre[i] = *(const float4*)&efeat[(size_t)eids_s[row] * EDGE_F + c4 * 4];
        }
    }
    #pragma unroll
    for (int i = 0; i < 3; i++) {
        int idx = t + i * L0_THREADS;
        if (idx < L0_TILE * 8) {
            int row = idx >> 3, c4 = idx & 7;
            int pos = row ^ (8 * (c4 & 3));
            AsT[0][4 * c4 + 0][pos] = pre[i].x;
            AsT[0][4 * c4 + 1][pos] = pre[i].y;
            AsT[0][4 * c4 + 2][pos] = pre[i].z;
            AsT[0][4 * c4 + 3][pos] = pre[i].w;
        }
    }
    // issue tile1's gather loads — in flight during tile0 compute
    #pragma unroll
    for (int i = 0; i < 3; i++) {
        int idx = t + i * L0_THREADS;
        if (idx < L0_TILE * 8) {
            int row = idx >> 3, c4 = idx & 7;
            pre[i] = *(const float4*)&efeat[(size_t)eids_s[L0_TILE + row] * EDGE_F + c4 * 4];
        }
    }
    __syncthreads();

    const int rt = t & 31;          // row tile 0..31 (4 rows each)
    const int ct = t >> 5;          // col tile 0..11 (4 cols each)
    const int r0 = rt * 4, c0 = ct * 4;

    const unsigned long long bias0 = pack2(bes[c0 + 0], bes[c0 + 1]);
    const unsigned long long bias1 = pack2(bes[c0 + 2], bes[c0 + 3]);

    #pragma unroll
    for (int tile = 0; tile < 2; tile++) {
        if (tile == 1) {
            // store prefetched tile1 (stores wait on the overlapped loads)
            #pragma unroll
            for (int i = 0; i < 3; i++) {
                int idx = t + i * L0_THREADS;
                if (idx < L0_TILE * 8) {
                    int row = idx >> 3, c4 = idx & 7;
                    int pos = row ^ (8 * (c4 & 3));
                    AsT[1][4 * c4 + 0][pos] = pre[i].x;
                    AsT[1][4 * c4 + 1][pos] = pre[i].y;
                    AsT[1][4 * c4 + 2][pos] = pre[i].z;
                    AsT[1][4 * c4 + 3][pos] = pre[i].w;
                }
            }
            __syncthreads();
        }
        const int base = tile * L0_TILE;

        unsigned long long acc2[4][2];
        #pragma unroll
        for (int m = 0; m < 4; m++) { acc2[m][0] = bias0; acc2[m][1] = bias1; }

        #pragma unroll 8
        for (int k = 0; k < EDGE_F; k++) {
            int rs = r0 ^ (8 * ((k >> 2) & 3));
            float4 av = *(const float4*)&AsT[tile][k][rs];
            ulonglong2 bA = *(const ulonglong2*)&Bs[k][c0];
            unsigned long long bb0 = bA.x, bb1 = bA.y;
            float a[4] = {av.x, av.y, av.z, av.w};
            #pragma unroll
            for (int m = 0; m < 4; m++) {
                unsigned long long am = pack2(a[m], a[m]);
                acc2[m][0] = fma2(am, bb0, acc2[m][0]);
                acc2[m][1] = fma2(am, bb1, acc2[m][1]);
            }
        }

        // epilogue: batch nfeat gathers, 4-row segment scan, red.v4 flush
        float4 nf[4];
        #pragma unroll
        for (int i = 0; i < 4; i++)
            nf[i] = *(const float4*)&nfeat[(size_t)srcs_s[base + r0 + i] * IN_F + c0];

        float s0 = 0.f, s1 = 0.f, s2 = 0.f, s3 = 0.f;
        int cur = dsts_s[base + r0];
        #pragma unroll
        for (int i = 0; i < 4; i++) {
            int d = dsts_s[base + r0 + i];
            if (d != cur) {
                red_add_v4(&g_hsum[(size_t)cur * IN_F + c0], s0, s1, s2, s3);
                s0 = s1 = s2 = s3 = 0.f;
                cur = d;
            }
            float2 e0 = unpack2(acc2[i][0]);
            float2 e1 = unpack2(acc2[i][1]);
            s0 = fmaf(fmaxf(e0.x, 0.f), nf[i].x, s0);
            s1 = fmaf(fmaxf(e0.y, 0.f), nf[i].y, s1);
            s2 = fmaf(fmaxf(e1.x, 0.f), nf[i].z, s2);
            s3 = fmaf(fmaxf(e1.y, 0.f), nf[i].w, s3);
        }
        red_add_v4(&g_hsum[(size_t)cur * IN_F + c0], s0, s1, s2, s3);
    }
}

// divide by degree + build concat h = [nfeat | mean]
__global__ void k_finalize0(const float* __restrict__ nfeat) {
    int i = blockIdx.x * blockDim.x + threadIdx.x;
    if (i >= N_NODES * IN_F) return;
    int n = i / IN_F, c = i % IN_F;
    int deg = g_rowptr[n + 1] - g_rowptr[n];
    float inv = 1.f / fmaxf((float)deg, 1.f);
    g_h[n * H0_F + c]        = nfeat[i];
    g_h[n * H0_F + IN_F + c] = g_hsum[i] * inv;
}

// ---------------- mean96: warp per node, float4 lanes (24 active) ----------------
__global__ void __launch_bounds__(256) k_mean96() {
    int gw = (blockIdx.x * blockDim.x + threadIdx.x) >> 5;
    int l  = threadIdx.x & 31;
    if (gw >= N_NODES || l >= 24) return;
    int beg = g_rowptr[gw], end = g_rowptr[gw + 1];
    float4 A = make_float4(0.f, 0.f, 0.f, 0.f);
    float4 B = make_float4(0.f, 0.f, 0.f, 0.f);
    int j = beg;
    for (; j + 2 <= end; j += 2) {
        float4 va = ((const float4*)&g_h[(size_t)g_csr[j].x     * H0_F])[l];
        float4 vb = ((const float4*)&g_h[(size_t)g_csr[j + 1].x * H0_F])[l];
        A.x += va.x; A.y += va.y; A.z += va.z; A.w += va.w;
        B.x += vb.x; B.y += vb.y; B.z += vb.z; B.w += vb.w;
    }
    if (j < end) {
        float4 va = ((const float4*)&g_h[(size_t)g_csr[j].x * H0_F])[l];
        A.x += va.x; A.y += va.y; A.z += va.z; A.w += va.w;
    }
    float inv = 1.f / fmaxf((float)(end - beg), 1.f);
    float4 r;
    r.x = (A.x + B.x) * inv; r.y = (A.y + B.y) * inv;
    r.z = (A.z + B.z) * inv; r.w = (A.w + B.w) * inv;
    ((float4*)&g_hn1[(size_t)gw * H0_F])[l] = r;
}

// ---------------- GEMM1: g_h1 = relu(g_h@W1s + g_hn1@W1n + b1), BK=48 ----------------
__global__ void __launch_bounds__(256) k_gemm1(
    const float* __restrict__ Wa, const float* __restrict__ Wb,
    const float* __restrict__ bias)
{
    constexpr int BM = 128, BK = 48, NOUT = HID_F, APAD = BM + 4;
    __shared__ float AsT[BK][APAD];
    __shared__ float Bs[BK][NOUT];

    int t  = threadIdx.x;
    int tx = t & 15, ty = t >> 4;
    int brow = blockIdx.x * BM;
    int r0 = ty * 8, c0 = tx * 8;

    unsigned long long acc2[8][4];
    #pragma unroll
    for (int m = 0; m < 8; m++)
        #pragma unroll
        for (int j = 0; j < 4; j++) acc2[m][j] = pack2(0.f, 0.f);

    #pragma unroll
    for (int phase = 0; phase < 2; phase++) {
        const float* A = phase ? g_hn1 : g_h;
        const float* W = phase ? Wb : Wa;
        for (int kt = 0; kt < H0_F; kt += BK) {
            // A tile: 128 rows x 48 k = 1536 float4s
            #pragma unroll
            for (int i = 0; i < 6; i++) {
                int idx = t + i * 256;
                int r = idx / 12, c4 = idx % 12;
                int grow = brow + r;
                float4 v = make_float4(0.f, 0.f, 0.f, 0.f);
                if (grow < N_NODES)
                    v = *(const float4*)&A[(size_t)grow * H0_F + kt + c4 * 4];
                int pos = r ^ (8 * (c4 & 3));
                AsT[4 * c4 + 0][pos] = v.x;
                AsT[4 * c4 + 1][pos] = v.y;
                AsT[4 * c4 + 2][pos] = v.z;
                AsT[4 * c4 + 3][pos] = v.w;
            }
            // B tile: 48 x 128 = 1536 float4s
            #pragma unroll
            for (int i = 0; i < 6; i++) {
                int idx = t + i * 256;
                int r = idx >> 5, c4 = idx & 31;
                *(float4*)&Bs[r][c4 * 4] = *(const float4*)&W[(size_t)(kt + r) * NOUT + c4 * 4];
            }
            __syncthreads();
            #pragma unroll 8
            for (int k = 0; k < BK; k++) {
                int rs = r0 ^ (8 * ((k >> 2) & 3));
                float4 alo = *(const float4*)&AsT[k][rs];
                float4 ahi = *(const float4*)&AsT[k][rs + 4];
                ulonglong2 bA = *(const ulonglong2*)&Bs[k][c0];
                ulonglong2 bB = *(const ulonglong2*)&Bs[k][c0 + 4];
                unsigned long long bb0 = bA.x, bb1 = bA.y, bb2 = bB.x, bb3 = bB.y;
                float a[8] = {alo.x, alo.y, alo.z, alo.w, ahi.x, ahi.y, ahi.z, ahi.w};
                #pragma unroll
                for (int m = 0; m < 8; m++) {
                    unsigned long long am = pack2(a[m], a[m]);
                    acc2[m][0] = fma2(am, bb0, acc2[m][0]);
                    acc2[m][1] = fma2(am, bb1, acc2[m][1]);
                    acc2[m][2] = fma2(am, bb2, acc2[m][2]);
                    acc2[m][3] = fma2(am, bb3, acc2[m][3]);
                }
            }
            __syncthreads();
        }
    }
    #pragma unroll
    for (int m = 0; m < 8; m++) {
        int grow = brow + r0 + m;
        if (grow < N_NODES) {
            #pragma unroll
            for (int j = 0; j < 4; j++) {
                float2 c2 = unpack2(acc2[m][j]);
                float v0 = fmaxf(c2.x + bias[c0 + 2 * j],     0.f);
                float v1 = fmaxf(c2.y + bias[c0 + 2 * j + 1], 0.f);
                *(float2*)&g_h1[(size_t)grow * HID_F + c0 + 2 * j] = make_float2(v0, v1);
            }
        }
    }
}

// ---------------- GEMM2: g_s2z = [h1@W2s + b2 | h1@W2n] ----------------
__global__ void __launch_bounds__(256) k_gemm2(
    const float* __restrict__ Wa, const float* __restrict__ Wb,
    const float* __restrict__ bias)
{
    constexpr int BM = 128, BK = 32, NOUT = 128, APAD = BM + 4;
    __shared__ float AsT[BK][APAD];
    __shared__ float Bs[BK][NOUT];

    int t  = threadIdx.x;
    int tx = t & 15, ty = t >> 4;
    int brow = blockIdx.x * BM;
    int r0 = ty * 8, c0 = tx * 8;

    unsigned long long acc2[8][4];
    #pragma unroll
    for (int m = 0; m < 8; m++)
        #pragma unroll
        for (int j = 0; j < 4; j++) acc2[m][j] = pack2(0.f, 0.f);

    for (int kt = 0; kt < HID_F; kt += BK) {
        #pragma unroll
        for (int i = 0; i < 4; i++) {
            int idx = t + i * 256;
            int r = idx >> 3, c4 = idx & 7;
            int grow = brow + r;
            float4 v = make_float4(0.f, 0.f, 0.f, 0.f);
            if (grow < N_NODES)
                v = *(const float4*)&g_h1[(size_t)grow * HID_F + kt + c4 * 4];
            int pos = r ^ (8 * (c4 & 3));
            AsT[4 * c4 + 0][pos] = v.x;
            AsT[4 * c4 + 1][pos] = v.y;
            AsT[4 * c4 + 2][pos] = v.z;
            AsT[4 * c4 + 3][pos] = v.w;
        }
        #pragma unroll
        for (int i = 0; i < 4; i++) {
            int idx = t + i * 256;
            int r = idx >> 5, c4 = idx & 31;
            float4 v;
            if (c4 < 16) v = *(const float4*)&Wa[(size_t)(kt + r) * OUT_F + c4 * 4];
            else         v = *(const float4*)&Wb[(size_t)(kt + r) * OUT_F + (c4 - 16) * 4];
            *(float4*)&Bs[r][c4 * 4] = v;
        }
        __syncthreads();
        #pragma unroll 8
        for (int k = 0; k < BK; k++) {
            int rs = r0 ^ (8 * ((k >> 2) & 3));
            float4 alo = *(const float4*)&AsT[k][rs];
            float4 ahi = *(const float4*)&AsT[k][rs + 4];
            ulonglong2 bA = *(const ulonglong2*)&Bs[k][c0];
            ulonglong2 bB = *(const ulonglong2*)&Bs[k][c0 + 4];
            unsigned long long bb0 = bA.x, bb1 = bA.y, bb2 = bB.x, bb3 = bB.y;
            float a[8] = {alo.x, alo.y, alo.z, alo.w, ahi.x, ahi.y, ahi.z, ahi.w};
            #pragma unroll
            for (int m = 0; m < 8; m++) {
                unsigned long long am = pack2(a[m], a[m]);
                acc2[m][0] = fma2(am, bb0, acc2[m][0]);
                acc2[m][1] = fma2(am, bb1, acc2[m][1]);
                acc2[m][2] = fma2(am, bb2, acc2[m][2]);
                acc2[m][3] = fma2(am, bb3, acc2[m][3]);
            }
        }
        __syncthreads();
    }
    #pragma unroll
    for (int m = 0; m < 8; m++) {
        int grow = brow + r0 + m;
        if (grow < N_NODES) {
            #pragma unroll
            for (int j = 0; j < 4; j++) {
                int col = c0 + 2 * j;
                float2 c2 = unpack2(acc2[m][j]);
                float v0 = c2.x + (col     < OUT_F ? bias[col]     : 0.f);
                float v1 = c2.y + (col + 1 < OUT_F ? bias[col + 1] : 0.f);
                *(float2*)&g_s2z[(size_t)grow * 128 + col] = make_float2(v0, v1);
            }
        }
    }
}

// ---------------- final: out = S2 + seg_mean(Z[src]); half-warp per node ----------------
__global__ void __launch_bounds__(256) k_final(float* __restrict__ out) {
    int gt  = blockIdx.x * blockDim.x + threadIdx.x;
    int ghw = gt >> 4;            // half-warp id = node
    int hl  = gt & 15;            // 16 lanes x float4 = 64 cols
    if (ghw >= N_NODES) return;
    int beg = g_rowptr[ghw], end = g_rowptr[ghw + 1];
    float4 A = make_float4(0.f, 0.f, 0.f, 0.f);
    float4 B = make_float4(0.f, 0.f, 0.f, 0.f);
    int j = beg;
    for (; j + 2 <= end; j += 2) {
        float4 va = ((const float4*)&g_s2z[(size_t)g_csr[j].x     * 128 + OUT_F])[hl];
        float4 vb = ((const float4*)&g_s2z[(size_t)g_csr[j + 1].x * 128 + OUT_F])[hl];
        A.x += va.x; A.y += va.y; A.z += va.z; A.w += va.w;
        B.x += vb.x; B.y += vb.y; B.z += vb.z; B.w += vb.w;
    }
    if (j < end) {
        float4 va = ((const float4*)&g_s2z[(size_t)g_csr[j].x * 128 + OUT_F])[hl];
        A.x += va.x; A.y += va.y; A.z += va.z; A.w += va.w;
    }
    float inv = 1.f / fmaxf((float)(end - beg), 1.f);
    float4 s2 = ((const float4*)&g_s2z[(size_t)ghw * 128])[hl];
    float4 r;
    r.x = s2.x + (A.x + B.x) * inv;
    r.y = s2.y + (A.y + B.y) * inv;
    r.z = s2.z + (A.z + B.z) * inv;
    r.w = s2.w + (A.w + B.w) * inv;
    ((float4*)&out[(size_t)ghw * OUT_F])[hl] = r;
}

// ---------------- launch ----------------
extern "C" void kernel_launch(void* const* d_in, const int* in_sizes, int n_in,
                              void* d_out, int out_size)
{
    const float* nfeat = (const float*)d_in[0];
    const float* efeat = (const float*)d_in[1];
    const int*   src   = (const int*)d_in[2];
    const int*   dst   = (const int*)d_in[3];
    const float* We    = (const float*)d_in[4];
    const float* be    = (const float*)d_in[5];
    const float* W1s   = (const float*)d_in[6];
    const float* W1n   = (const float*)d_in[7];
    const float* b1    = (const float*)d_in[8];
    const float* W2s   = (const float*)d_in[9];
    const float* W2n   = (const float*)d_in[10];
    const float* b2    = (const float*)d_in[11];
    float* out = (float*)d_out;

    const int WARP_GRID = (N_NODES * 32 + 255) / 256;   // warp-per-node kernels
    const int HW_GRID   = (N_NODES * 16 + 255) / 256;   // half-warp-per-node

    void* p = nullptr;
    cudaGetSymbolAddress(&p, g_deg);
    cudaMemsetAsync(p, 0, N_NODES * sizeof(int));
    cudaGetSymbolAddress(&p, g_hsum);
    cudaMemsetAsync(p, 0, (size_t)N_NODES * IN_F * sizeof(float));

    k_deg<<<(N_EDGES + 255) / 256, 256>>>(dst);
    k_scan_blocks<<<SCAN_NB, 1024>>>();
    k_scan_top<<<1, 32>>>();
    k_scan_add<<<SCAN_NB, 1024>>>();
    k_fill<<<(N_EDGES + 255) / 256, 256>>>(src, dst);
    k_layer0_gemm<<<N_EDGES / (2 * L0_TILE), L0_THREADS>>>(nfeat, efeat, We, be);
    k_finalize0<<<(N_NODES * IN_F + 255) / 256, 256>>>(nfeat);
    k_mean96<<<WARP_GRID, 256>>>();
    k_gemm1<<<(N_NODES + 127) / 128, 256>>>(W1s, W1n, b1);
    k_gemm2<<<(N_NODES + 127) / 128, 256>>>(W2s, W2n, b2);
    k_final<<<HW_GRID, 256>>>(out);
}